// round 1
// baseline (speedup 1.0000x reference)
#include <cuda_runtime.h>
#include <math.h>
#include <stdint.h>

// ---------------------------------------------------------------------------
// Problem constants (Gemma2 decoder layer)
// ---------------------------------------------------------------------------
#define S_LEN   2048
#define H_DIM   3584
#define NH      16
#define NKV     8
#define HD      256
#define NQD     (NH * HD)     // 4096
#define NKVD    (NKV * HD)    // 2048
#define I_DIM   14336
#define SCALE_F 0.0625f       // 256^-0.5
#define SOFTCAP 50.0f
#define EPS_F   1e-6f

// ---------------------------------------------------------------------------
// Device scratch (static device globals; runtime allocation is forbidden)
// ---------------------------------------------------------------------------
__device__ float g_h   [(size_t)S_LEN * H_DIM];     // normed hidden / reused
__device__ float g_q   [(size_t)S_LEN * NQD];
__device__ float g_k   [(size_t)S_LEN * NKVD];
__device__ float g_v   [(size_t)S_LEN * NKVD];
__device__ float g_sc  [(size_t)NH * S_LEN * S_LEN]; // scores/probs, 256 MB
__device__ float g_at  [(size_t)S_LEN * NQD];
__device__ float g_tmp [(size_t)S_LEN * H_DIM];
__device__ float g_x1  [(size_t)S_LEN * H_DIM];
__device__ float g_gate[(size_t)S_LEN * I_DIM];
__device__ float g_up  [(size_t)S_LEN * I_DIM];

// ---------------------------------------------------------------------------
// Block reductions
// ---------------------------------------------------------------------------
template<bool IS_MAX>
__device__ __forceinline__ float block_reduce(float v) {
    __shared__ float sh[8];
    __syncthreads();                      // guard against back-to-back reuse
    int lane = threadIdx.x & 31, wid = threadIdx.x >> 5;
    #pragma unroll
    for (int o = 16; o; o >>= 1) {
        float t = __shfl_xor_sync(0xffffffffu, v, o);
        v = IS_MAX ? fmaxf(v, t) : (v + t);
    }
    if (lane == 0) sh[wid] = v;
    __syncthreads();
    if (wid == 0) {
        float r = (threadIdx.x < 8) ? sh[threadIdx.x]
                                    : (IS_MAX ? -3.4e38f : 0.0f);
        #pragma unroll
        for (int o = 4; o; o >>= 1) {
            float t = __shfl_xor_sync(0xffffffffu, r, o);
            r = IS_MAX ? fmaxf(r, t) : (r + t);
        }
        if (lane == 0) sh[0] = r;
    }
    __syncthreads();
    return sh[0];
}

// ---------------------------------------------------------------------------
// Generic tiled SGEMM: C[M,N] = A[M,K] * op(B)
//   TB=false: B is [K,N] row-major (ldb = row stride)
//   TB=true : B is [N,K] row-major, used transposed (C = A * B^T)
//   CMODE 0: plain; 1: skip C tiles entirely above the diagonal (scores);
//   CMODE 2: clip K loop to brow*128+128 (PV with lower-triangular A)
// Assumes M,N multiples of 128 and K multiple of 8 (true for all calls here).
// blockIdx.z batches: A += z*sA, B += (z/zdivB)*sB, C += z*sC.
// ---------------------------------------------------------------------------
template<bool TB, int CMODE>
__global__ void __launch_bounds__(256)
gemm_kernel(const float* __restrict__ A, const float* __restrict__ B,
            float* __restrict__ C,
            int M, int N, int K, int lda, int ldb, int ldc,
            long long sA, long long sB, long long sC, int zdivB)
{
    const int bz = blockIdx.z;
    A += (long long)bz * sA;
    B += (long long)(bz / zdivB) * sB;
    C += (long long)bz * sC;

    const int brow = blockIdx.y, bcol = blockIdx.x;
    if (CMODE == 1 && bcol > brow) return;   // tile fully masked (j > i)

    int kEnd = K;
    if (CMODE == 2) kEnd = min(K, brow * 128 + 128);

    __shared__ float As[8][128];
    __shared__ float Bs[8][128];

    const int tid = threadIdx.x;
    const int ty = tid >> 4, tx = tid & 15;

    // A loader: 128 rows x 8 cols, float4 along K
    const int a_r = tid >> 1, a_k = (tid & 1) * 4;
    const float* Aptr = A + (long long)(brow * 128 + a_r) * lda + a_k;

    float acc[8][8];
    #pragma unroll
    for (int i = 0; i < 8; i++)
        #pragma unroll
        for (int j = 0; j < 8; j++) acc[i][j] = 0.0f;

    for (int k0 = 0; k0 < kEnd; k0 += 8) {
        float4 av = *(const float4*)(Aptr + k0);
        As[a_k + 0][a_r] = av.x; As[a_k + 1][a_r] = av.y;
        As[a_k + 2][a_r] = av.z; As[a_k + 3][a_r] = av.w;

        if (TB) {
            const int b_n = tid >> 1, b_k = (tid & 1) * 4;
            float4 bv = *(const float4*)(B + (long long)(bcol * 128 + b_n) * ldb + k0 + b_k);
            Bs[b_k + 0][b_n] = bv.x; Bs[b_k + 1][b_n] = bv.y;
            Bs[b_k + 2][b_n] = bv.z; Bs[b_k + 3][b_n] = bv.w;
        } else {
            const int b_k = tid >> 5, b_n = (tid & 31) * 4;
            float4 bv = *(const float4*)(B + (long long)(k0 + b_k) * ldb + bcol * 128 + b_n);
            *(float4*)&Bs[b_k][b_n] = bv;
        }
        __syncthreads();

        #pragma unroll
        for (int kk = 0; kk < 8; kk++) {
            float4 a0 = *(const float4*)&As[kk][ty * 8];
            float4 a1 = *(const float4*)&As[kk][ty * 8 + 4];
            float4 b0 = *(const float4*)&Bs[kk][tx * 8];
            float4 b1 = *(const float4*)&Bs[kk][tx * 8 + 4];
            float af[8] = {a0.x, a0.y, a0.z, a0.w, a1.x, a1.y, a1.z, a1.w};
            float bf[8] = {b0.x, b0.y, b0.z, b0.w, b1.x, b1.y, b1.z, b1.w};
            #pragma unroll
            for (int i = 0; i < 8; i++)
                #pragma unroll
                for (int j = 0; j < 8; j++)
                    acc[i][j] = fmaf(af[i], bf[j], acc[i][j]);
        }
        __syncthreads();
    }

    #pragma unroll
    for (int i = 0; i < 8; i++) {
        float* crow = C + (long long)(brow * 128 + ty * 8 + i) * ldc + bcol * 128 + tx * 8;
        *(float4*)(crow)     = make_float4(acc[i][0], acc[i][1], acc[i][2], acc[i][3]);
        *(float4*)(crow + 4) = make_float4(acc[i][4], acc[i][5], acc[i][6], acc[i][7]);
    }
}

// ---------------------------------------------------------------------------
// RMSNorm: out = x * rsqrt(mean(x^2) + eps) * w        (one block per row)
// ---------------------------------------------------------------------------
__global__ void rmsnorm_kernel(const float* __restrict__ x,
                               const float* __restrict__ w,
                               float* __restrict__ out)
{
    const size_t base = (size_t)blockIdx.x * H_DIM;
    float ss = 0.0f;
    for (int j = threadIdx.x; j < H_DIM; j += blockDim.x) {
        float v = x[base + j];
        ss += v * v;
    }
    ss = block_reduce<false>(ss);
    const float inv = rsqrtf(ss / (float)H_DIM + EPS_F);
    for (int j = threadIdx.x; j < H_DIM; j += blockDim.x)
        out[base + j] = x[base + j] * inv * w[j];
}

// out = resid + rms_norm(t, w)
__global__ void add_rmsnorm_kernel(const float* __restrict__ resid,
                                   const float* __restrict__ t,
                                   const float* __restrict__ w,
                                   float* __restrict__ out)
{
    const size_t base = (size_t)blockIdx.x * H_DIM;
    float ss = 0.0f;
    for (int j = threadIdx.x; j < H_DIM; j += blockDim.x) {
        float v = t[base + j];
        ss += v * v;
    }
    ss = block_reduce<false>(ss);
    const float inv = rsqrtf(ss / (float)H_DIM + EPS_F);
    for (int j = threadIdx.x; j < H_DIM; j += blockDim.x)
        out[base + j] = resid[base + j] + t[base + j] * inv * w[j];
}

// ---------------------------------------------------------------------------
// RoPE on q [S, NH, HD] and k [S, NKV, HD]; positions = arange(S).
// rotate-half pairing: (d, d+HD/2), angle = pos * theta^(-d/(HD/2)/... )
// inv_freq[d] = 10000^(-(2d)/HD) = 10000^(-d/128)
// ---------------------------------------------------------------------------
__global__ void rope_kernel(float* __restrict__ q, float* __restrict__ k)
{
    const int p = blockIdx.x;
    const int total = (NH + NKV) * 128;   // 3072 (head, d) pairs
    for (int t = threadIdx.x; t < total; t += blockDim.x) {
        const int d = t & 127;
        const float inv = powf(10000.0f, -(float)d * (1.0f / 128.0f));
        float sn, cs;
        sincosf((float)p * inv, &sn, &cs);
        float* rowp;
        if (t < NH * 128) {
            const int head = t >> 7;
            rowp = q + (size_t)p * NQD + head * HD + d;
        } else {
            const int head = (t - NH * 128) >> 7;
            rowp = k + (size_t)p * NKVD + head * HD + d;
        }
        const float a = rowp[0], b = rowp[128];
        rowp[0]   = a * cs - b * sn;
        rowp[128] = b * cs + a * sn;
    }
}

// ---------------------------------------------------------------------------
// Softcap + causal softmax, in place on g_sc[h][i][:]; zero tail (j > i).
// ---------------------------------------------------------------------------
__global__ void softmax_kernel(float* __restrict__ sc)
{
    const int i = blockIdx.x, h = blockIdx.y;
    float* row = sc + ((size_t)h * S_LEN + i) * S_LEN;
    const int n = i + 1;

    float mx = -3.4e38f;
    for (int j = threadIdx.x; j < n; j += blockDim.x) {
        float xv = row[j] * SCALE_F;
        xv = tanhf(xv * (1.0f / SOFTCAP)) * SOFTCAP;
        row[j] = xv;
        mx = fmaxf(mx, xv);
    }
    mx = block_reduce<true>(mx);

    float sm = 0.0f;
    for (int j = threadIdx.x; j < n; j += blockDim.x) {
        float e = expf(row[j] - mx);
        row[j] = e;
        sm += e;
    }
    sm = block_reduce<false>(sm);
    const float invs = 1.0f / sm;

    for (int j = threadIdx.x; j < n; j += blockDim.x) row[j] *= invs;
    for (int j = n + threadIdx.x; j < S_LEN; j += blockDim.x) row[j] = 0.0f;
}

// ---------------------------------------------------------------------------
// g = gelu_tanh(g) * u   (elementwise over S*I)
// ---------------------------------------------------------------------------
__global__ void gelumul_kernel(float* __restrict__ g, const float* __restrict__ u,
                               int nTot)
{
    const int stride = gridDim.x * blockDim.x;
    for (int i = blockIdx.x * blockDim.x + threadIdx.x; i < nTot; i += stride) {
        float xv = g[i];
        float inner = 0.7978845608028654f * (xv + 0.044715f * xv * xv * xv);
        g[i] = 0.5f * xv * (1.0f + tanhf(inner)) * u[i];
    }
}

// ---------------------------------------------------------------------------
// Host launcher
// ---------------------------------------------------------------------------
extern "C" void kernel_launch(void* const* d_in, const int* in_sizes, int n_in,
                              void* d_out, int out_size)
{
    // Identify inputs by element count (order-invariant between dict order and
    // function-signature order; relative order within each size class matches
    // both conventions).
    const float *x = nullptr, *w_in = nullptr, *w_pa = nullptr, *w_pf = nullptr,
                *w_pff = nullptr, *wq = nullptr, *wk = nullptr, *wv = nullptr,
                *wo = nullptr, *wg = nullptr, *wu = nullptr, *wd = nullptr;
    int c7 = 0, c14 = 0, c3584 = 0, c51 = 0;
    for (int i = 0; i < n_in; i++) {
        const int s = in_sizes[i];
        const float* p = (const float*)d_in[i];
        if (s == S_LEN * H_DIM) {                 // 7,340,032: hidden, wk, wv
            if (c7 == 0) x = p; else if (c7 == 1) wk = p; else wv = p;
            c7++;
        } else if (s == H_DIM * NQD) {            // 14,680,064: wq, wo
            if (c14 == 0) wq = p; else wo = p;
            c14++;
        } else if (s == H_DIM) {                  // 3584: the 4 norm weights
            if (c3584 == 0) w_in = p; else if (c3584 == 1) w_pa = p;
            else if (c3584 == 2) w_pf = p; else w_pff = p;
            c3584++;
        } else if (s == H_DIM * I_DIM) {          // 51,380,224: gate, up, down
            if (c51 == 0) wg = p; else if (c51 == 1) wu = p; else wd = p;
            c51++;
        }
        // position_ids (2048) and attention_mask (4,194,304) ignored:
        // positions are arange(S) and window(4096) >= S => pure causal.
    }

    float *h_, *q_, *k_, *v_, *sc_, *at_, *tm_, *x1_, *ga_, *up_;
    cudaGetSymbolAddress((void**)&h_,  g_h);
    cudaGetSymbolAddress((void**)&q_,  g_q);
    cudaGetSymbolAddress((void**)&k_,  g_k);
    cudaGetSymbolAddress((void**)&v_,  g_v);
    cudaGetSymbolAddress((void**)&sc_, g_sc);
    cudaGetSymbolAddress((void**)&at_, g_at);
    cudaGetSymbolAddress((void**)&tm_, g_tmp);
    cudaGetSymbolAddress((void**)&x1_, g_x1);
    cudaGetSymbolAddress((void**)&ga_, g_gate);
    cudaGetSymbolAddress((void**)&up_, g_up);

    const long long SS = (long long)S_LEN * S_LEN;

    // 1) pre-attn norm
    rmsnorm_kernel<<<S_LEN, 256>>>(x, w_in, h_);

    // 2) QKV projections
    gemm_kernel<false, 0><<<dim3(NQD / 128, S_LEN / 128, 1), 256>>>(
        h_, wq, q_, S_LEN, NQD, H_DIM, H_DIM, NQD, NQD, 0, 0, 0, 1);
    gemm_kernel<false, 0><<<dim3(NKVD / 128, S_LEN / 128, 1), 256>>>(
        h_, wk, k_, S_LEN, NKVD, H_DIM, H_DIM, NKVD, NKVD, 0, 0, 0, 1);
    gemm_kernel<false, 0><<<dim3(NKVD / 128, S_LEN / 128, 1), 256>>>(
        h_, wv, v_, S_LEN, NKVD, H_DIM, H_DIM, NKVD, NKVD, 0, 0, 0, 1);

    // 3) RoPE
    rope_kernel<<<S_LEN, 256>>>(q_, k_);

    // 4) scores = Q Kh^T per head (z = q head; kv head = z/2), causal tile skip
    gemm_kernel<true, 1><<<dim3(S_LEN / 128, S_LEN / 128, NH), 256>>>(
        q_, k_, sc_, S_LEN, S_LEN, HD, NQD, NKVD, S_LEN,
        (long long)HD, (long long)HD, SS, 2);

    // 5) softcap + causal softmax (in place)
    softmax_kernel<<<dim3(S_LEN, NH), 256>>>(sc_);

    // 6) attn = P @ Vh per head (K loop clipped by causality)
    gemm_kernel<false, 2><<<dim3(HD / 128, S_LEN / 128, NH), 256>>>(
        sc_, v_, at_, S_LEN, HD, S_LEN, S_LEN, NKVD, NQD,
        SS, (long long)HD, (long long)HD, 2);

    // 7) output projection
    gemm_kernel<false, 0><<<dim3(H_DIM / 128, S_LEN / 128, 1), 256>>>(
        at_, wo, tm_, S_LEN, H_DIM, NQD, NQD, H_DIM, H_DIM, 0, 0, 0, 1);

    // 8) x1 = x + rms_norm(attn_out, w_post_attn)
    add_rmsnorm_kernel<<<S_LEN, 256>>>(x, tm_, w_pa, x1_);

    // 9) pre-FF norm
    rmsnorm_kernel<<<S_LEN, 256>>>(x1_, w_pf, h_);

    // 10) gate / up projections
    gemm_kernel<false, 0><<<dim3(I_DIM / 128, S_LEN / 128, 1), 256>>>(
        h_, wg, ga_, S_LEN, I_DIM, H_DIM, H_DIM, I_DIM, I_DIM, 0, 0, 0, 1);
    gemm_kernel<false, 0><<<dim3(I_DIM / 128, S_LEN / 128, 1), 256>>>(
        h_, wu, up_, S_LEN, I_DIM, H_DIM, H_DIM, I_DIM, I_DIM, 0, 0, 0, 1);

    // 11) gelu_tanh(gate) * up
    {
        const int nTot = S_LEN * I_DIM;
        gelumul_kernel<<<(nTot + 255) / 256, 256>>>(ga_, up_, nTot);
    }

    // 12) down projection
    gemm_kernel<false, 0><<<dim3(H_DIM / 128, S_LEN / 128, 1), 256>>>(
        ga_, wd, tm_, S_LEN, H_DIM, I_DIM, I_DIM, H_DIM, H_DIM, 0, 0, 0, 1);

    // 13) out = x1 + rms_norm(ff_out, w_post_ff)
    add_rmsnorm_kernel<<<S_LEN, 256>>>(x1_, tm_, w_pff, (float*)d_out);

    (void)n_in; (void)out_size;
}

// round 2
// speedup vs baseline: 1.5516x; 1.5516x over previous
#include <cuda_runtime.h>
#include <cuda_bf16.h>
#include <math.h>
#include <stdint.h>

// ---------------------------------------------------------------------------
// Problem constants (Gemma2 decoder layer)
// ---------------------------------------------------------------------------
#define S_LEN   2048
#define H_DIM   3584
#define NH      16
#define NKV     8
#define HD      256
#define NQD     (NH * HD)     // 4096
#define NKVD    (NKV * HD)    // 2048
#define I_DIM   14336
#define SCALE_F 0.0625f       // 256^-0.5
#define SOFTCAP 50.0f
#define EPS_F   1e-6f

// ---------------------------------------------------------------------------
// Device scratch (static device globals; runtime allocation is forbidden)
// ---------------------------------------------------------------------------
__device__ float g_h   [(size_t)S_LEN * H_DIM];
__device__ float g_q   [(size_t)S_LEN * NQD];
__device__ float g_k   [(size_t)S_LEN * NKVD];
__device__ float g_v   [(size_t)S_LEN * NKVD];
__device__ float g_sc  [(size_t)NH * S_LEN * S_LEN]; // 256 MB scores/probs
__device__ float g_at  [(size_t)S_LEN * NQD];
__device__ float g_tmp [(size_t)S_LEN * H_DIM];
__device__ float g_x1  [(size_t)S_LEN * H_DIM];
__device__ float g_gate[(size_t)S_LEN * I_DIM];
__device__ float g_up  [(size_t)S_LEN * I_DIM];

// ---------------------------------------------------------------------------
// Block reductions
// ---------------------------------------------------------------------------
template<bool IS_MAX>
__device__ __forceinline__ float block_reduce(float v) {
    __shared__ float sh[8];
    __syncthreads();
    int lane = threadIdx.x & 31, wid = threadIdx.x >> 5;
    #pragma unroll
    for (int o = 16; o; o >>= 1) {
        float t = __shfl_xor_sync(0xffffffffu, v, o);
        v = IS_MAX ? fmaxf(v, t) : (v + t);
    }
    if (lane == 0) sh[wid] = v;
    __syncthreads();
    if (wid == 0) {
        float r = (threadIdx.x < 8) ? sh[threadIdx.x]
                                    : (IS_MAX ? -3.4e38f : 0.0f);
        #pragma unroll
        for (int o = 4; o; o >>= 1) {
            float t = __shfl_xor_sync(0xffffffffu, r, o);
            r = IS_MAX ? fmaxf(r, t) : (r + t);
        }
        if (lane == 0) sh[0] = r;
    }
    __syncthreads();
    return sh[0];
}

// ---------------------------------------------------------------------------
// bf16 helpers
// ---------------------------------------------------------------------------
__device__ __forceinline__ uint32_t bpack(float a, float b) {
    __nv_bfloat162 t = __floats2bfloat162_rn(a, b);   // .x=a (low), .y=b (high)
    return *reinterpret_cast<uint32_t*>(&t);
}

// split fp32 -> (hi, lo) bf16
__device__ __forceinline__ void bsplit(float x, __nv_bfloat16& h, __nv_bfloat16& l) {
    h = __float2bfloat16_rn(x);
    l = __float2bfloat16_rn(x - __bfloat162float(h));
}

__device__ __forceinline__ void mma_bf16(float* c, const uint32_t* a, const uint32_t* b) {
    asm volatile(
        "mma.sync.aligned.m16n8k16.row.col.f32.bf16.bf16.f32 "
        "{%0,%1,%2,%3}, {%4,%5,%6,%7}, {%8,%9}, {%0,%1,%2,%3};\n"
        : "+f"(c[0]), "+f"(c[1]), "+f"(c[2]), "+f"(c[3])
        : "r"(a[0]), "r"(a[1]), "r"(a[2]), "r"(a[3]), "r"(b[0]), "r"(b[1]));
}

// ---------------------------------------------------------------------------
// Tensor-core GEMM with split-bf16 (3-MMA) fp32 emulation.
//   C[M,N] = A[M,K] * op(B)
//   TB=false: B is [K,N] row-major; TB=true: B is [N,K] row-major (C=A*B^T)
//   CMODE 0: plain; 1: skip tiles above diagonal; 2: clip K to brow*128+128
// Block tile 128x128, K-tile 32, 256 threads (8 warps of 32x64).
// All M,N multiples of 128; K multiples of 32.
// blockIdx.z batching: A += z*sA, B += (z/zdivB)*sB, C += z*sC.
// ---------------------------------------------------------------------------
#define ROWB 40                       // padded bf16 row length (conflict-free)
#define ARR_B (128 * ROWB)            // bf16 elems per smem array
#define STAGE_B (4 * ARR_B)           // Ah, Al, Bh, Bl
#define SMEM_BYTES (2 * STAGE_B * 2)  // 2 stages * bytes

template<bool TB, int CMODE>
__global__ void __launch_bounds__(256)
gemm_mma_kernel(const float* __restrict__ A, const float* __restrict__ B,
                float* __restrict__ C,
                int M, int N, int K, int lda, int ldb, int ldc,
                long long sA, long long sB, long long sC, int zdivB)
{
    const int bz = blockIdx.z;
    A += (long long)bz * sA;
    B += (long long)(bz / zdivB) * sB;
    C += (long long)bz * sC;

    const int brow = blockIdx.y, bcol = blockIdx.x;
    if (CMODE == 1 && bcol > brow) return;

    int kEnd = K;
    if (CMODE == 2) kEnd = min(K, brow * 128 + 128);
    const int nk = kEnd >> 5;            // K-tiles of 32

    extern __shared__ __nv_bfloat16 smem[];
    // stage s arrays: Ah, Al, Bh, Bl
    __nv_bfloat16* Ah[2] = { smem,             smem + STAGE_B };
    __nv_bfloat16* Al[2] = { Ah[0] + ARR_B,    Ah[1] + ARR_B };
    __nv_bfloat16* Bh[2] = { Al[0] + ARR_B,    Al[1] + ARR_B };
    __nv_bfloat16* Bl[2] = { Bh[0] + ARR_B,    Bh[1] + ARR_B };

    const int tid  = threadIdx.x;
    const int lane = tid & 31;
    const int wid  = tid >> 5;
    const int warp_m = (wid & 3) * 32;   // 4 warps along M
    const int warp_n = (wid >> 2) * 64;  // 2 warps along N

    // ---- gmem tile loaders (into regs) ----
    // A-like tile (and TB B): [128 rows][32 cols] fp32, row = t/8 + i*32, col = 4*(t%8)
    const int lr = tid >> 3;             // 0..31
    const int lc = (tid & 7) * 4;        // 0..28

    float4 va[4], vb[4];

    auto loadA = [&](int k0) {
        const float* base = A + (long long)(brow * 128 + lr) * lda + k0 + lc;
        #pragma unroll
        for (int i = 0; i < 4; i++)
            va[i] = *(const float4*)(base + (long long)(i * 32) * lda);
    };
    auto loadB = [&](int k0) {
        if (TB) {
            const float* base = B + (long long)(bcol * 128 + lr) * ldb + k0 + lc;
            #pragma unroll
            for (int i = 0; i < 4; i++)
                vb[i] = *(const float4*)(base + (long long)(i * 32) * ldb);
        } else {
            // [32 k][128 n] fp32: k = t/8, cols = 4*(t%8) + 32*i
            const float* base = B + (long long)(k0 + lr) * ldb + bcol * 128 + lc;
            #pragma unroll
            for (int i = 0; i < 4; i++)
                vb[i] = *(const float4*)(base + i * 32);
        }
    };
    auto storeA = [&](int s) {
        #pragma unroll
        for (int i = 0; i < 4; i++) {
            const int off = (lr + i * 32) * ROWB + lc;
            __nv_bfloat16 h0,h1,h2,h3,l0,l1,l2,l3;
            bsplit(va[i].x,h0,l0); bsplit(va[i].y,h1,l1);
            bsplit(va[i].z,h2,l2); bsplit(va[i].w,h3,l3);
            *(uint2*)(Ah[s] + off) = make_uint2(
                bpack(__bfloat162float(h0), __bfloat162float(h1)),
                bpack(__bfloat162float(h2), __bfloat162float(h3)));
            *(uint2*)(Al[s] + off) = make_uint2(
                bpack(__bfloat162float(l0), __bfloat162float(l1)),
                bpack(__bfloat162float(l2), __bfloat162float(l3)));
        }
    };
    auto storeB = [&](int s) {
        if (TB) {
            #pragma unroll
            for (int i = 0; i < 4; i++) {
                const int off = (lr + i * 32) * ROWB + lc;
                __nv_bfloat16 h0,h1,h2,h3,l0,l1,l2,l3;
                bsplit(vb[i].x,h0,l0); bsplit(vb[i].y,h1,l1);
                bsplit(vb[i].z,h2,l2); bsplit(vb[i].w,h3,l3);
                *(uint2*)(Bh[s] + off) = make_uint2(
                    bpack(__bfloat162float(h0), __bfloat162float(h1)),
                    bpack(__bfloat162float(h2), __bfloat162float(h3)));
                *(uint2*)(Bl[s] + off) = make_uint2(
                    bpack(__bfloat162float(l0), __bfloat162float(l1)),
                    bpack(__bfloat162float(l2), __bfloat162float(l3)));
            }
        } else {
            // transpose-store: Bs[n][k]
            #pragma unroll
            for (int i = 0; i < 4; i++) {
                const float* pv = &vb[i].x;
                #pragma unroll
                for (int j = 0; j < 4; j++) {
                    const int n = lc + j + i * 32;   // wait: cols = lc + 32*i
                    __nv_bfloat16 h, l;
                    bsplit(pv[j], h, l);
                    Bh[s][n * ROWB + lr] = h;
                    Bl[s][n * ROWB + lr] = l;
                }
            }
        }
    };

    float acc[2][8][4];
    #pragma unroll
    for (int mi = 0; mi < 2; mi++)
        #pragma unroll
        for (int ni = 0; ni < 8; ni++)
            #pragma unroll
            for (int r = 0; r < 4; r++) acc[mi][ni][r] = 0.0f;

    const int fr = lane >> 2;            // 0..7
    const int fc = (lane & 3) * 2;       // 0,2,4,6

    auto compute = [&](int s) {
        #pragma unroll
        for (int kk = 0; kk < 32; kk += 16) {
            uint32_t ah[2][4], al[2][4], bhf[8][2], blf[8][2];
            #pragma unroll
            for (int mi = 0; mi < 2; mi++) {
                const int r0 = warp_m + mi * 16 + fr;
                const int c0 = kk + fc;
                ah[mi][0] = *(const uint32_t*)(Ah[s] + r0 * ROWB + c0);
                ah[mi][1] = *(const uint32_t*)(Ah[s] + (r0 + 8) * ROWB + c0);
                ah[mi][2] = *(const uint32_t*)(Ah[s] + r0 * ROWB + c0 + 8);
                ah[mi][3] = *(const uint32_t*)(Ah[s] + (r0 + 8) * ROWB + c0 + 8);
                al[mi][0] = *(const uint32_t*)(Al[s] + r0 * ROWB + c0);
                al[mi][1] = *(const uint32_t*)(Al[s] + (r0 + 8) * ROWB + c0);
                al[mi][2] = *(const uint32_t*)(Al[s] + r0 * ROWB + c0 + 8);
                al[mi][3] = *(const uint32_t*)(Al[s] + (r0 + 8) * ROWB + c0 + 8);
            }
            #pragma unroll
            for (int ni = 0; ni < 8; ni++) {
                const int n0 = warp_n + ni * 8 + fr;
                const int c0 = kk + fc;
                bhf[ni][0] = *(const uint32_t*)(Bh[s] + n0 * ROWB + c0);
                bhf[ni][1] = *(const uint32_t*)(Bh[s] + n0 * ROWB + c0 + 8);
                blf[ni][0] = *(const uint32_t*)(Bl[s] + n0 * ROWB + c0);
                blf[ni][1] = *(const uint32_t*)(Bl[s] + n0 * ROWB + c0 + 8);
            }
            #pragma unroll
            for (int mi = 0; mi < 2; mi++)
                #pragma unroll
                for (int ni = 0; ni < 8; ni++)
                    mma_bf16(acc[mi][ni], ah[mi], bhf[ni]);
            #pragma unroll
            for (int mi = 0; mi < 2; mi++)
                #pragma unroll
                for (int ni = 0; ni < 8; ni++)
                    mma_bf16(acc[mi][ni], ah[mi], blf[ni]);
            #pragma unroll
            for (int mi = 0; mi < 2; mi++)
                #pragma unroll
                for (int ni = 0; ni < 8; ni++)
                    mma_bf16(acc[mi][ni], al[mi], bhf[ni]);
        }
    };

    // ---- pipelined main loop ----
    loadA(0); loadB(0);
    storeA(0); storeB(0);
    __syncthreads();

    for (int kt = 0; kt < nk; kt++) {
        const int cur = kt & 1;
        const bool more = (kt + 1 < nk);
        if (more) { loadA((kt + 1) << 5); loadB((kt + 1) << 5); }
        compute(cur);
        if (more) { storeA(cur ^ 1); storeB(cur ^ 1); }
        __syncthreads();
    }

    // ---- epilogue ----
    #pragma unroll
    for (int mi = 0; mi < 2; mi++) {
        const int row = brow * 128 + warp_m + mi * 16 + fr;
        #pragma unroll
        for (int ni = 0; ni < 8; ni++) {
            const int col = bcol * 128 + warp_n + ni * 8 + fc;
            float* p0 = C + (long long)row * ldc + col;
            float* p1 = C + (long long)(row + 8) * ldc + col;
            p0[0] = acc[mi][ni][0]; p0[1] = acc[mi][ni][1];
            p1[0] = acc[mi][ni][2]; p1[1] = acc[mi][ni][3];
        }
    }
}

// ---------------------------------------------------------------------------
// RMSNorm kernels
// ---------------------------------------------------------------------------
__global__ void rmsnorm_kernel(const float* __restrict__ x,
                               const float* __restrict__ w,
                               float* __restrict__ out)
{
    const size_t base = (size_t)blockIdx.x * H_DIM;
    float ss = 0.0f;
    for (int j = threadIdx.x; j < H_DIM; j += blockDim.x) {
        float v = x[base + j];
        ss += v * v;
    }
    ss = block_reduce<false>(ss);
    const float inv = rsqrtf(ss / (float)H_DIM + EPS_F);
    for (int j = threadIdx.x; j < H_DIM; j += blockDim.x)
        out[base + j] = x[base + j] * inv * w[j];
}

__global__ void add_rmsnorm_kernel(const float* __restrict__ resid,
                                   const float* __restrict__ t,
                                   const float* __restrict__ w,
                                   float* __restrict__ out)
{
    const size_t base = (size_t)blockIdx.x * H_DIM;
    float ss = 0.0f;
    for (int j = threadIdx.x; j < H_DIM; j += blockDim.x) {
        float v = t[base + j];
        ss += v * v;
    }
    ss = block_reduce<false>(ss);
    const float inv = rsqrtf(ss / (float)H_DIM + EPS_F);
    for (int j = threadIdx.x; j < H_DIM; j += blockDim.x)
        out[base + j] = resid[base + j] + t[base + j] * inv * w[j];
}

// ---------------------------------------------------------------------------
// RoPE (positions = arange(S))
// ---------------------------------------------------------------------------
__global__ void rope_kernel(float* __restrict__ q, float* __restrict__ k)
{
    const int p = blockIdx.x;
    const int total = (NH + NKV) * 128;
    for (int t = threadIdx.x; t < total; t += blockDim.x) {
        const int d = t & 127;
        const float inv = powf(10000.0f, -(float)d * (1.0f / 128.0f));
        float sn, cs;
        sincosf((float)p * inv, &sn, &cs);
        float* rowp;
        if (t < NH * 128) {
            const int head = t >> 7;
            rowp = q + (size_t)p * NQD + head * HD + d;
        } else {
            const int head = (t - NH * 128) >> 7;
            rowp = k + (size_t)p * NKVD + head * HD + d;
        }
        const float a = rowp[0], b = rowp[128];
        rowp[0]   = a * cs - b * sn;
        rowp[128] = b * cs + a * sn;
    }
}

// ---------------------------------------------------------------------------
// Softcap + causal softmax (in place), zero tail
// ---------------------------------------------------------------------------
__global__ void softmax_kernel(float* __restrict__ sc)
{
    const int i = blockIdx.x, h = blockIdx.y;
    float* row = sc + ((size_t)h * S_LEN + i) * S_LEN;
    const int n = i + 1;

    float mx = -3.4e38f;
    for (int j = threadIdx.x; j < n; j += blockDim.x) {
        float xv = row[j] * SCALE_F;
        xv = tanhf(xv * (1.0f / SOFTCAP)) * SOFTCAP;
        row[j] = xv;
        mx = fmaxf(mx, xv);
    }
    mx = block_reduce<true>(mx);

    float sm = 0.0f;
    for (int j = threadIdx.x; j < n; j += blockDim.x) {
        float e = expf(row[j] - mx);
        row[j] = e;
        sm += e;
    }
    sm = block_reduce<false>(sm);
    const float invs = 1.0f / sm;

    for (int j = threadIdx.x; j < n; j += blockDim.x) row[j] *= invs;
    for (int j = n + threadIdx.x; j < S_LEN; j += blockDim.x) row[j] = 0.0f;
}

// ---------------------------------------------------------------------------
// g = gelu_tanh(g) * u
// ---------------------------------------------------------------------------
__global__ void gelumul_kernel(float* __restrict__ g, const float* __restrict__ u,
                               int nTot)
{
    const int stride = gridDim.x * blockDim.x;
    for (int i = blockIdx.x * blockDim.x + threadIdx.x; i < nTot; i += stride) {
        float xv = g[i];
        float inner = 0.7978845608028654f * (xv + 0.044715f * xv * xv * xv);
        g[i] = 0.5f * xv * (1.0f + tanhf(inner)) * u[i];
    }
}

// ---------------------------------------------------------------------------
// Host launcher
// ---------------------------------------------------------------------------
extern "C" void kernel_launch(void* const* d_in, const int* in_sizes, int n_in,
                              void* d_out, int out_size)
{
    const float *x = nullptr, *w_in = nullptr, *w_pa = nullptr, *w_pf = nullptr,
                *w_pff = nullptr, *wq = nullptr, *wk = nullptr, *wv = nullptr,
                *wo = nullptr, *wg = nullptr, *wu = nullptr, *wd = nullptr;
    int c7 = 0, c14 = 0, c3584 = 0, c51 = 0;
    for (int i = 0; i < n_in; i++) {
        const int s = in_sizes[i];
        const float* p = (const float*)d_in[i];
        if (s == S_LEN * H_DIM) {
            if (c7 == 0) x = p; else if (c7 == 1) wk = p; else wv = p;
            c7++;
        } else if (s == H_DIM * NQD) {
            if (c14 == 0) wq = p; else wo = p;
            c14++;
        } else if (s == H_DIM) {
            if (c3584 == 0) w_in = p; else if (c3584 == 1) w_pa = p;
            else if (c3584 == 2) w_pf = p; else w_pff = p;
            c3584++;
        } else if (s == H_DIM * I_DIM) {
            if (c51 == 0) wg = p; else if (c51 == 1) wu = p; else wd = p;
            c51++;
        }
    }

    float *h_, *q_, *k_, *v_, *sc_, *at_, *tm_, *x1_, *ga_, *up_;
    cudaGetSymbolAddress((void**)&h_,  g_h);
    cudaGetSymbolAddress((void**)&q_,  g_q);
    cudaGetSymbolAddress((void**)&k_,  g_k);
    cudaGetSymbolAddress((void**)&v_,  g_v);
    cudaGetSymbolAddress((void**)&sc_, g_sc);
    cudaGetSymbolAddress((void**)&at_, g_at);
    cudaGetSymbolAddress((void**)&tm_, g_tmp);
    cudaGetSymbolAddress((void**)&x1_, g_x1);
    cudaGetSymbolAddress((void**)&ga_, g_gate);
    cudaGetSymbolAddress((void**)&up_, g_up);

    // allow 80KB dynamic smem on the GEMM kernels (cheap; done every call)
    cudaFuncSetAttribute(gemm_mma_kernel<false,0>,
                         cudaFuncAttributeMaxDynamicSharedMemorySize, SMEM_BYTES);
    cudaFuncSetAttribute(gemm_mma_kernel<true,1>,
                         cudaFuncAttributeMaxDynamicSharedMemorySize, SMEM_BYTES);
    cudaFuncSetAttribute(gemm_mma_kernel<false,2>,
                         cudaFuncAttributeMaxDynamicSharedMemorySize, SMEM_BYTES);

    const long long SS = (long long)S_LEN * S_LEN;

    // 1) pre-attn norm
    rmsnorm_kernel<<<S_LEN, 256>>>(x, w_in, h_);

    // 2) QKV projections
    gemm_mma_kernel<false,0><<<dim3(NQD/128, S_LEN/128, 1), 256, SMEM_BYTES>>>(
        h_, wq, q_, S_LEN, NQD, H_DIM, H_DIM, NQD, NQD, 0, 0, 0, 1);
    gemm_mma_kernel<false,0><<<dim3(NKVD/128, S_LEN/128, 1), 256, SMEM_BYTES>>>(
        h_, wk, k_, S_LEN, NKVD, H_DIM, H_DIM, NKVD, NKVD, 0, 0, 0, 1);
    gemm_mma_kernel<false,0><<<dim3(NKVD/128, S_LEN/128, 1), 256, SMEM_BYTES>>>(
        h_, wv, v_, S_LEN, NKVD, H_DIM, H_DIM, NKVD, NKVD, 0, 0, 0, 1);

    // 3) RoPE
    rope_kernel<<<S_LEN, 256>>>(q_, k_);

    // 4) scores = Q Kh^T per head, causal tile skip
    gemm_mma_kernel<true,1><<<dim3(S_LEN/128, S_LEN/128, NH), 256, SMEM_BYTES>>>(
        q_, k_, sc_, S_LEN, S_LEN, HD, NQD, NKVD, S_LEN,
        (long long)HD, (long long)HD, SS, 2);

    // 5) softcap + causal softmax
    softmax_kernel<<<dim3(S_LEN, NH), 256>>>(sc_);

    // 6) attn = P @ Vh per head (K clipped by causality)
    gemm_mma_kernel<false,2><<<dim3(HD/128, S_LEN/128, NH), 256, SMEM_BYTES>>>(
        sc_, v_, at_, S_LEN, HD, S_LEN, S_LEN, NKVD, NQD,
        SS, (long long)HD, (long long)HD, 2);

    // 7) output projection
    gemm_mma_kernel<false,0><<<dim3(H_DIM/128, S_LEN/128, 1), 256, SMEM_BYTES>>>(
        at_, wo, tm_, S_LEN, H_DIM, NQD, NQD, H_DIM, H_DIM, 0, 0, 0, 1);

    // 8) x1 = x + rms_norm(attn_out)
    add_rmsnorm_kernel<<<S_LEN, 256>>>(x, tm_, w_pa, x1_);

    // 9) pre-FF norm
    rmsnorm_kernel<<<S_LEN, 256>>>(x1_, w_pf, h_);

    // 10) gate / up projections
    gemm_mma_kernel<false,0><<<dim3(I_DIM/128, S_LEN/128, 1), 256, SMEM_BYTES>>>(
        h_, wg, ga_, S_LEN, I_DIM, H_DIM, H_DIM, I_DIM, I_DIM, 0, 0, 0, 1);
    gemm_mma_kernel<false,0><<<dim3(I_DIM/128, S_LEN/128, 1), 256, SMEM_BYTES>>>(
        h_, wu, up_, S_LEN, I_DIM, H_DIM, H_DIM, I_DIM, I_DIM, 0, 0, 0, 1);

    // 11) gelu_tanh(gate) * up
    {
        const int nTot = S_LEN * I_DIM;
        gelumul_kernel<<<(nTot + 255) / 256, 256>>>(ga_, up_, nTot);
    }

    // 12) down projection
    gemm_mma_kernel<false,0><<<dim3(H_DIM/128, S_LEN/128, 1), 256, SMEM_BYTES>>>(
        ga_, wd, tm_, S_LEN, H_DIM, I_DIM, I_DIM, H_DIM, H_DIM, 0, 0, 0, 1);

    // 13) out = x1 + rms_norm(ff_out)
    add_rmsnorm_kernel<<<S_LEN, 256>>>(x1_, tm_, w_pff, (float*)d_out);

    (void)n_in; (void)out_size;
}

// round 4
// speedup vs baseline: 2.5636x; 1.6522x over previous
#include <cuda_runtime.h>
#include <cuda_bf16.h>
#include <math.h>
#include <stdint.h>

// ---------------------------------------------------------------------------
// Problem constants (Gemma2 decoder layer)
// ---------------------------------------------------------------------------
#define S_LEN   2048
#define H_DIM   3584
#define NH      16
#define NKV     8
#define HD      256
#define NQD     (NH * HD)     // 4096
#define NKVD    (NKV * HD)    // 2048
#define I_DIM   14336
#define SCALE_F 0.0625f
#define SOFTCAP 50.0f
#define EPS_F   1e-6f

typedef __nv_bfloat16 bf16;

// ---------------------------------------------------------------------------
// Device scratch (static; runtime allocation is forbidden)
// ---------------------------------------------------------------------------
__device__ float g_q   [(size_t)S_LEN * NQD];
__device__ float g_k   [(size_t)S_LEN * NKVD];
__device__ float g_v   [(size_t)S_LEN * NKVD];
__device__ float g_sc  [(size_t)NH * S_LEN * S_LEN];
__device__ float g_at  [(size_t)S_LEN * NQD];
__device__ float g_tmp [(size_t)S_LEN * H_DIM];
__device__ float g_x1  [(size_t)S_LEN * H_DIM];
__device__ float g_gate[(size_t)S_LEN * I_DIM];
__device__ float g_up  [(size_t)S_LEN * I_DIM];

__device__ bf16 s_wqt_h[(size_t)NQD * H_DIM],  s_wqt_l[(size_t)NQD * H_DIM];
__device__ bf16 s_wkt_h[(size_t)NKVD * H_DIM], s_wkt_l[(size_t)NKVD * H_DIM];
__device__ bf16 s_wvt_h[(size_t)NKVD * H_DIM], s_wvt_l[(size_t)NKVD * H_DIM];
__device__ bf16 s_wot_h[(size_t)H_DIM * NQD],  s_wot_l[(size_t)H_DIM * NQD];
__device__ bf16 s_wgt_h[(size_t)I_DIM * H_DIM], s_wgt_l[(size_t)I_DIM * H_DIM];
__device__ bf16 s_wut_h[(size_t)I_DIM * H_DIM], s_wut_l[(size_t)I_DIM * H_DIM];
__device__ bf16 s_wdt_h[(size_t)H_DIM * I_DIM], s_wdt_l[(size_t)H_DIM * I_DIM];
__device__ bf16 s_hh[(size_t)S_LEN * H_DIM],   s_hl[(size_t)S_LEN * H_DIM];
__device__ bf16 s_qh[(size_t)S_LEN * NQD],     s_ql[(size_t)S_LEN * NQD];
__device__ bf16 s_kh[(size_t)S_LEN * NKVD],    s_kl[(size_t)S_LEN * NKVD];
__device__ bf16 s_vth[(size_t)NKVD * S_LEN],   s_vtl[(size_t)NKVD * S_LEN];
__device__ bf16 s_ph[(size_t)NH * S_LEN * S_LEN], s_pl[(size_t)NH * S_LEN * S_LEN];
__device__ bf16 s_ath[(size_t)S_LEN * NQD],    s_atl[(size_t)S_LEN * NQD];
__device__ bf16 s_guh[(size_t)S_LEN * I_DIM],  s_gul[(size_t)S_LEN * I_DIM];

// ---------------------------------------------------------------------------
// helpers
// ---------------------------------------------------------------------------
__device__ __forceinline__ void bsplit(float x, bf16& h, bf16& l) {
    h = __float2bfloat16_rn(x);
    l = __float2bfloat16_rn(x - __bfloat162float(h));
}

template<bool IS_MAX>
__device__ __forceinline__ float block_reduce(float v) {
    __shared__ float sh[8];
    __syncthreads();
    int lane = threadIdx.x & 31, wid = threadIdx.x >> 5;
    #pragma unroll
    for (int o = 16; o; o >>= 1) {
        float t = __shfl_xor_sync(0xffffffffu, v, o);
        v = IS_MAX ? fmaxf(v, t) : (v + t);
    }
    if (lane == 0) sh[wid] = v;
    __syncthreads();
    if (wid == 0) {
        float r = (threadIdx.x < 8) ? sh[threadIdx.x] : (IS_MAX ? -3.4e38f : 0.0f);
        #pragma unroll
        for (int o = 4; o; o >>= 1) {
            float t = __shfl_xor_sync(0xffffffffu, r, o);
            r = IS_MAX ? fmaxf(r, t) : (r + t);
        }
        if (lane == 0) sh[0] = r;
    }
    __syncthreads();
    return sh[0];
}

__device__ __forceinline__ uint32_t smem_u32(const void* p) {
    uint32_t a;
    asm("{ .reg .u64 t; cvta.to.shared.u64 t, %1; cvt.u32.u64 %0, t; }" : "=r"(a) : "l"(p));
    return a;
}

#define CP16(dst, src) \
    asm volatile("cp.async.cg.shared.global [%0], [%1], 16;" \
                 :: "r"(dst), "l"(__cvta_generic_to_global(src)))
#define CP_COMMIT() asm volatile("cp.async.commit_group;" ::: "memory")
#define CP_WAIT2()  asm volatile("cp.async.wait_group 2;" ::: "memory")

__device__ __forceinline__ void mma_bf16(float* c, const uint32_t* a, const uint32_t* b) {
    asm volatile(
        "mma.sync.aligned.m16n8k16.row.col.f32.bf16.bf16.f32 "
        "{%0,%1,%2,%3}, {%4,%5,%6,%7}, {%8,%9}, {%0,%1,%2,%3};\n"
        : "+f"(c[0]), "+f"(c[1]), "+f"(c[2]), "+f"(c[3])
        : "r"(a[0]), "r"(a[1]), "r"(a[2]), "r"(a[3]), "r"(b[0]), "r"(b[1]));
}

// ---------------------------------------------------------------------------
// mma.sync GEMM:  C[M, N] = A[M, K] * B[N, K]^T   (A,B bf16 hi/lo; C fp32)
//   CTA tile 128(M) x 256(N) x 32(K), 8 warps (2M x 4N) of 64x64.
//   cp.async 3-stage pipeline. Split-bf16 3-product emulation.
//   Smem per k16 plane: [rows][32B], 16B chunk XOR-swizzled by (row>>2)&1.
//   CMODE 0 plain; 1 causal tile skip; 2 K clipped to brow*128+128.
//   grid = (M/128 [fast], N/256, Z).
// ---------------------------------------------------------------------------
#define STG_BYTES 49152          // A 16KB + B 32KB
#define GEMM_SMEM (3 * STG_BYTES)

template<int CMODE>
__global__ void __launch_bounds__(256, 1)
gemm_mma(const bf16* __restrict__ Agh, const bf16* __restrict__ Agl,
         const bf16* __restrict__ Bgh, const bf16* __restrict__ Bgl,
         float* __restrict__ C, int K, int lda, int ldb, int ldc,
         long long sA, long long sB, long long sC, int zdivB)
{
    const int brow = blockIdx.x, bcol = blockIdx.y, bz = blockIdx.z;
    if (CMODE == 1 && 2 * bcol > brow) return;

    Agh += (long long)bz * sA;  Agl += (long long)bz * sA;
    Bgh += (long long)(bz / zdivB) * sB;  Bgl += (long long)(bz / zdivB) * sB;
    C   += (long long)bz * sC;

    int kEnd = K;
    if (CMODE == 2) kEnd = min(K, brow * 128 + 128);
    const int nk = kEnd >> 5;

    extern __shared__ char smem[];
    const uint32_t smb = smem_u32(smem);

    const int tid  = threadIdx.x;
    const int lane = tid & 31;
    const int wid  = tid >> 5;
    const int warp_m = (wid & 1) * 64;    // 2 warps along M
    const int warp_n = (wid >> 1) * 64;   // 4 warps along N
    const int fr  = lane >> 2;            // 0..7
    const int fcb = (lane & 3) * 4;       // byte offset within 16B chunk
    const int fc  = (lane & 3) * 2;       // element col offset

    // ---- stage loader (cp.async) ----
    auto load_stage = [&](int kt, int buf) {
        const uint32_t sb = smb + buf * STG_BYTES;
        const int k0 = kt << 5;
        #pragma unroll
        for (int it = 0; it < 2; it++) {            // A: 512 chunks
            const int idx = tid + it * 256;
            const int r = idx >> 2, q = idx & 3, h = q >> 1, cg = q & 1;
            const int cs = cg ^ ((r >> 2) & 1);
            const uint32_t d = sb + h * 8192 + r * 32 + cs * 16;
            const long long g = (long long)(brow * 128 + r) * lda + k0 + h * 16 + cg * 8;
            CP16(d,        Agh + g);
            CP16(d + 4096, Agl + g);
        }
        #pragma unroll
        for (int it = 0; it < 4; it++) {            // B: 1024 chunks
            const int idx = tid + it * 256;
            const int r = idx >> 2, q = idx & 3, h = q >> 1, cg = q & 1;
            const int cs = cg ^ ((r >> 2) & 1);
            const uint32_t d = sb + 16384 + h * 16384 + r * 32 + cs * 16;
            const long long g = (long long)(bcol * 256 + r) * ldb + k0 + h * 16 + cg * 8;
            CP16(d,        Bgh + g);
            CP16(d + 8192, Bgl + g);
        }
    };

    float acc[4][8][4];
    #pragma unroll
    for (int mi = 0; mi < 4; mi++)
        #pragma unroll
        for (int ni = 0; ni < 8; ni++)
            #pragma unroll
            for (int r = 0; r < 4; r++) acc[mi][ni][r] = 0.0f;

    auto ld32 = [&](uint32_t off) -> uint32_t {
        return *(const uint32_t*)(smem + off);
    };

    auto compute_stage = [&](int buf) {
        const uint32_t sb = (uint32_t)(buf * STG_BYTES);
        #pragma unroll
        for (int h = 0; h < 2; h++) {               // two k16 halves
            const uint32_t aph = sb + h * 8192;     // A hi plane
            const uint32_t apl = aph + 4096;        // A lo plane
            const uint32_t bph = sb + 16384 + h * 16384;
            const uint32_t bpl = bph + 8192;

            uint32_t ah[4][4], al[4][4];
            #pragma unroll
            for (int mi = 0; mi < 4; mi++) {
                const int r = warp_m + mi * 16 + fr;
                const uint32_t p = (uint32_t)(((r >> 2) & 1) * 16);
                const uint32_t o0 = r * 32 + p + fcb;          // k chunk 0
                const uint32_t o1 = r * 32 + (p ^ 16) + fcb;   // k chunk 1
                ah[mi][0] = ld32(aph + o0); ah[mi][1] = ld32(aph + o0 + 256);
                ah[mi][2] = ld32(aph + o1); ah[mi][3] = ld32(aph + o1 + 256);
                al[mi][0] = ld32(apl + o0); al[mi][1] = ld32(apl + o0 + 256);
                al[mi][2] = ld32(apl + o1); al[mi][3] = ld32(apl + o1 + 256);
            }
            #pragma unroll
            for (int ni = 0; ni < 8; ni++) {
                const int rb = warp_n + ni * 8 + fr;
                const uint32_t p = (uint32_t)(((rb >> 2) & 1) * 16);
                const uint32_t o0 = rb * 32 + p + fcb;
                const uint32_t o1 = rb * 32 + (p ^ 16) + fcb;
                uint32_t bh[2] = { ld32(bph + o0), ld32(bph + o1) };
                uint32_t bl[2] = { ld32(bpl + o0), ld32(bpl + o1) };
                #pragma unroll
                for (int mi = 0; mi < 4; mi++) {
                    mma_bf16(acc[mi][ni], ah[mi], bh);
                    mma_bf16(acc[mi][ni], al[mi], bh);
                    mma_bf16(acc[mi][ni], ah[mi], bl);
                }
            }
        }
    };

    // ---- 3-stage pipeline ----
    {
        int s = 0;
        for (; s < 3 && s < nk; s++) { load_stage(s, s); CP_COMMIT(); }
        for (; s < 3; s++) CP_COMMIT();
    }
    for (int kt = 0; kt < nk; kt++) {
        CP_WAIT2();
        __syncthreads();
        compute_stage(kt % 3);
        __syncthreads();
        if (kt + 3 < nk) load_stage(kt + 3, kt % 3);
        CP_COMMIT();
    }

    // ---- epilogue ----
    #pragma unroll
    for (int mi = 0; mi < 4; mi++) {
        const long long row = (long long)(brow * 128 + warp_m + mi * 16 + fr);
        #pragma unroll
        for (int ni = 0; ni < 8; ni++) {
            const long long col = (long long)(bcol * 256 + warp_n + ni * 8 + fc);
            *(float2*)(C + row * ldc + col) =
                make_float2(acc[mi][ni][0], acc[mi][ni][1]);
            *(float2*)(C + (row + 8) * ldc + col) =
                make_float2(acc[mi][ni][2], acc[mi][ni][3]);
        }
    }
}

// ---------------------------------------------------------------------------
// Transpose + split:  W[Kd, Nd] fp32  ->  T[Nd, Kd] bf16 hi/lo
// ---------------------------------------------------------------------------
__global__ void tsplit_kernel(const float* __restrict__ W,
                              bf16* __restrict__ Th, bf16* __restrict__ Tl,
                              int Kd, int Nd)
{
    __shared__ float t[32][33];
    const int n0 = blockIdx.x * 32, k0 = blockIdx.y * 32;
    const int tx = threadIdx.x, ty = threadIdx.y;
    #pragma unroll
    for (int i = 0; i < 4; i++)
        t[ty + i * 8][tx] = W[(long long)(k0 + ty + i * 8) * Nd + n0 + tx];
    __syncthreads();
    #pragma unroll
    for (int i = 0; i < 4; i++) {
        const float v = t[tx][ty + i * 8];
        bf16 h, l; bsplit(v, h, l);
        const long long o = (long long)(n0 + ty + i * 8) * Kd + k0 + tx;
        Th[o] = h; Tl[o] = l;
    }
}

__global__ void split_kernel(const float* __restrict__ x,
                             bf16* __restrict__ oh, bf16* __restrict__ ol, int n)
{
    const int stride = gridDim.x * blockDim.x;
    for (int i = blockIdx.x * blockDim.x + threadIdx.x; i < n; i += stride) {
        bf16 h, l; bsplit(x[i], h, l);
        oh[i] = h; ol[i] = l;
    }
}

// ---------------------------------------------------------------------------
// RMSNorm variants
// ---------------------------------------------------------------------------
__global__ void rmsnorm_split_kernel(const float* __restrict__ x,
                                     const float* __restrict__ w,
                                     bf16* __restrict__ oh, bf16* __restrict__ ol)
{
    const size_t base = (size_t)blockIdx.x * H_DIM;
    float ss = 0.0f;
    for (int j = threadIdx.x; j < H_DIM; j += blockDim.x) {
        float v = x[base + j]; ss += v * v;
    }
    ss = block_reduce<false>(ss);
    const float inv = rsqrtf(ss / (float)H_DIM + EPS_F);
    for (int j = threadIdx.x; j < H_DIM; j += blockDim.x) {
        bf16 h, l; bsplit(x[base + j] * inv * w[j], h, l);
        oh[base + j] = h; ol[base + j] = l;
    }
}

__global__ void add_rmsnorm_kernel(const float* __restrict__ resid,
                                   const float* __restrict__ t,
                                   const float* __restrict__ w,
                                   float* __restrict__ out)
{
    const size_t base = (size_t)blockIdx.x * H_DIM;
    float ss = 0.0f;
    for (int j = threadIdx.x; j < H_DIM; j += blockDim.x) {
        float v = t[base + j]; ss += v * v;
    }
    ss = block_reduce<false>(ss);
    const float inv = rsqrtf(ss / (float)H_DIM + EPS_F);
    for (int j = threadIdx.x; j < H_DIM; j += blockDim.x)
        out[base + j] = resid[base + j] + t[base + j] * inv * w[j];
}

// ---------------------------------------------------------------------------
// RoPE + split (positions = arange(S))
// ---------------------------------------------------------------------------
__global__ void rope_split_kernel(const float* __restrict__ q, const float* __restrict__ k,
                                  bf16* __restrict__ qh, bf16* __restrict__ ql,
                                  bf16* __restrict__ kh, bf16* __restrict__ kl)
{
    const int p = blockIdx.x;
    const int total = (NH + NKV) * 128;
    for (int t = threadIdx.x; t < total; t += blockDim.x) {
        const int d = t & 127;
        const float inv = powf(10000.0f, -(float)d * (1.0f / 128.0f));
        float sn, cs; sincosf((float)p * inv, &sn, &cs);
        size_t base; const float* src;
        bf16 *dh, *dl;
        if (t < NH * 128) {
            base = (size_t)p * NQD + (t >> 7) * HD + d;
            src = q; dh = qh; dl = ql;
        } else {
            base = (size_t)p * NKVD + ((t - NH * 128) >> 7) * HD + d;
            src = k; dh = kh; dl = kl;
        }
        const float a = src[base], b = src[base + 128];
        bf16 h, l;
        bsplit(a * cs - b * sn, h, l); dh[base] = h;       dl[base] = l;
        bsplit(b * cs + a * sn, h, l); dh[base + 128] = h; dl[base + 128] = l;
    }
}

// ---------------------------------------------------------------------------
// Softcap + causal softmax -> probs bf16 hi/lo (tail zeroed)
// ---------------------------------------------------------------------------
__global__ void softmax_split_kernel(float* __restrict__ sc,
                                     bf16* __restrict__ ph, bf16* __restrict__ pl)
{
    const int i = blockIdx.x, h = blockIdx.y;
    const size_t base = ((size_t)h * S_LEN + i) * S_LEN;
    float* row = sc + base;
    const int n = i + 1;

    float mx = -3.4e38f;
    for (int j = threadIdx.x; j < n; j += blockDim.x) {
        float xv = row[j] * SCALE_F;
        xv = tanhf(xv * (1.0f / SOFTCAP)) * SOFTCAP;
        row[j] = xv;
        mx = fmaxf(mx, xv);
    }
    mx = block_reduce<true>(mx);

    float sm = 0.0f;
    for (int j = threadIdx.x; j < n; j += blockDim.x) {
        float e = expf(row[j] - mx);
        row[j] = e;
        sm += e;
    }
    sm = block_reduce<false>(sm);
    const float invs = 1.0f / sm;

    for (int j = threadIdx.x; j < n; j += blockDim.x) {
        bf16 hh, ll; bsplit(row[j] * invs, hh, ll);
        ph[base + j] = hh; pl[base + j] = ll;
    }
    const bf16 z = __float2bfloat16(0.0f);
    for (int j = n + threadIdx.x; j < S_LEN; j += blockDim.x) {
        ph[base + j] = z; pl[base + j] = z;
    }
}

// ---------------------------------------------------------------------------
// gelu_tanh(gate) * up -> split
// ---------------------------------------------------------------------------
__global__ void gelumul_split_kernel(const float* __restrict__ g, const float* __restrict__ u,
                                     bf16* __restrict__ oh, bf16* __restrict__ ol, int n)
{
    const int stride = gridDim.x * blockDim.x;
    for (int i = blockIdx.x * blockDim.x + threadIdx.x; i < n; i += stride) {
        const float xv = g[i];
        const float inner = 0.7978845608028654f * (xv + 0.044715f * xv * xv * xv);
        const float r = 0.5f * xv * (1.0f + tanhf(inner)) * u[i];
        bf16 h, l; bsplit(r, h, l);
        oh[i] = h; ol[i] = l;
    }
}

// ---------------------------------------------------------------------------
// Host launcher
// ---------------------------------------------------------------------------
#define SYM(v, s) do { cudaGetSymbolAddress((void**)&(v), s); } while (0)

extern "C" void kernel_launch(void* const* d_in, const int* in_sizes, int n_in,
                              void* d_out, int out_size)
{
    const float *x = nullptr, *w_in = nullptr, *w_pa = nullptr, *w_pf = nullptr,
                *w_pff = nullptr, *wq = nullptr, *wk = nullptr, *wv = nullptr,
                *wo = nullptr, *wg = nullptr, *wu = nullptr, *wd = nullptr;
    int c7 = 0, c14 = 0, c3584 = 0, c51 = 0;
    for (int i = 0; i < n_in; i++) {
        const int s = in_sizes[i];
        const float* p = (const float*)d_in[i];
        if (s == S_LEN * H_DIM) {
            if (c7 == 0) x = p; else if (c7 == 1) wk = p; else wv = p;
            c7++;
        } else if (s == H_DIM * NQD) {
            if (c14 == 0) wq = p; else wo = p;
            c14++;
        } else if (s == H_DIM) {
            if (c3584 == 0) w_in = p; else if (c3584 == 1) w_pa = p;
            else if (c3584 == 2) w_pf = p; else w_pff = p;
            c3584++;
        } else if (s == H_DIM * I_DIM) {
            if (c51 == 0) wg = p; else if (c51 == 1) wu = p; else wd = p;
            c51++;
        }
    }

    float *q_, *k_, *v_, *sc_, *at_, *tm_, *x1_, *ga_, *up_;
    SYM(q_, g_q); SYM(k_, g_k); SYM(v_, g_v); SYM(sc_, g_sc); SYM(at_, g_at);
    SYM(tm_, g_tmp); SYM(x1_, g_x1); SYM(ga_, g_gate); SYM(up_, g_up);

    bf16 *wqt_h, *wqt_l, *wkt_h, *wkt_l, *wvt_h, *wvt_l, *wot_h, *wot_l;
    bf16 *wgt_h, *wgt_l, *wut_h, *wut_l, *wdt_h, *wdt_l;
    bf16 *hh, *hl, *qh, *ql, *kh, *kl, *vth, *vtl, *ph, *pl, *ath, *atl, *guh, *gul;
    SYM(wqt_h, s_wqt_h); SYM(wqt_l, s_wqt_l); SYM(wkt_h, s_wkt_h); SYM(wkt_l, s_wkt_l);
    SYM(wvt_h, s_wvt_h); SYM(wvt_l, s_wvt_l); SYM(wot_h, s_wot_h); SYM(wot_l, s_wot_l);
    SYM(wgt_h, s_wgt_h); SYM(wgt_l, s_wgt_l); SYM(wut_h, s_wut_h); SYM(wut_l, s_wut_l);
    SYM(wdt_h, s_wdt_h); SYM(wdt_l, s_wdt_l);
    SYM(hh, s_hh); SYM(hl, s_hl); SYM(qh, s_qh); SYM(ql, s_ql);
    SYM(kh, s_kh); SYM(kl, s_kl); SYM(vth, s_vth); SYM(vtl, s_vtl);
    SYM(ph, s_ph); SYM(pl, s_pl); SYM(ath, s_ath); SYM(atl, s_atl);
    SYM(guh, s_guh); SYM(gul, s_gul);

    cudaFuncSetAttribute(gemm_mma<0>, cudaFuncAttributeMaxDynamicSharedMemorySize, GEMM_SMEM);
    cudaFuncSetAttribute(gemm_mma<1>, cudaFuncAttributeMaxDynamicSharedMemorySize, GEMM_SMEM);
    cudaFuncSetAttribute(gemm_mma<2>, cudaFuncAttributeMaxDynamicSharedMemorySize, GEMM_SMEM);

    const dim3 tb(32, 8);
    const long long SS = (long long)S_LEN * S_LEN;

    // ---- weight transpose + split ----
    tsplit_kernel<<<dim3(NQD/32,  H_DIM/32), tb>>>(wq, wqt_h, wqt_l, H_DIM, NQD);
    tsplit_kernel<<<dim3(NKVD/32, H_DIM/32), tb>>>(wk, wkt_h, wkt_l, H_DIM, NKVD);
    tsplit_kernel<<<dim3(NKVD/32, H_DIM/32), tb>>>(wv, wvt_h, wvt_l, H_DIM, NKVD);
    tsplit_kernel<<<dim3(H_DIM/32, NQD/32),  tb>>>(wo, wot_h, wot_l, NQD, H_DIM);
    tsplit_kernel<<<dim3(I_DIM/32, H_DIM/32), tb>>>(wg, wgt_h, wgt_l, H_DIM, I_DIM);
    tsplit_kernel<<<dim3(I_DIM/32, H_DIM/32), tb>>>(wu, wut_h, wut_l, H_DIM, I_DIM);
    tsplit_kernel<<<dim3(H_DIM/32, I_DIM/32), tb>>>(wd, wdt_h, wdt_l, I_DIM, H_DIM);

    // 1) pre-attn norm (-> hi/lo)
    rmsnorm_split_kernel<<<S_LEN, 256>>>(x, w_in, hh, hl);

    // 2) QKV projections
    gemm_mma<0><<<dim3(16, NQD/256, 1), 256, GEMM_SMEM>>>(
        hh, hl, wqt_h, wqt_l, q_, H_DIM, H_DIM, H_DIM, NQD, 0, 0, 0, 1);
    gemm_mma<0><<<dim3(16, NKVD/256, 1), 256, GEMM_SMEM>>>(
        hh, hl, wkt_h, wkt_l, k_, H_DIM, H_DIM, H_DIM, NKVD, 0, 0, 0, 1);
    gemm_mma<0><<<dim3(16, NKVD/256, 1), 256, GEMM_SMEM>>>(
        hh, hl, wvt_h, wvt_l, v_, H_DIM, H_DIM, H_DIM, NKVD, 0, 0, 0, 1);

    // 3) RoPE (+split); V transpose (+split)
    rope_split_kernel<<<S_LEN, 256>>>(q_, k_, qh, ql, kh, kl);
    tsplit_kernel<<<dim3(NKVD/32, S_LEN/32), tb>>>(v_, vth, vtl, S_LEN, NKVD);

    // 4) scores = Q K^T per head (causal tile skip)
    gemm_mma<1><<<dim3(16, S_LEN/256, NH), 256, GEMM_SMEM>>>(
        qh, ql, kh, kl, sc_, HD, NQD, NKVD, S_LEN,
        (long long)HD, (long long)HD, SS, 2);

    // 5) softcap + softmax (-> probs hi/lo)
    softmax_split_kernel<<<dim3(S_LEN, NH), 256>>>(sc_, ph, pl);

    // 6) attn = P @ V per head (K clipped by causality)
    gemm_mma<2><<<dim3(16, 1, NH), 256, GEMM_SMEM>>>(
        ph, pl, vth, vtl, at_, S_LEN, S_LEN, S_LEN, NQD,
        SS, (long long)HD * S_LEN, (long long)HD, 2);

    // 7) output projection
    split_kernel<<<2048, 256>>>(at_, ath, atl, S_LEN * NQD);
    gemm_mma<0><<<dim3(16, H_DIM/256, 1), 256, GEMM_SMEM>>>(
        ath, atl, wot_h, wot_l, tm_, NQD, NQD, NQD, H_DIM, 0, 0, 0, 1);

    // 8) x1 = x + rms_norm(attn_out)
    add_rmsnorm_kernel<<<S_LEN, 256>>>(x, tm_, w_pa, x1_);

    // 9) pre-FF norm (-> hi/lo)
    rmsnorm_split_kernel<<<S_LEN, 256>>>(x1_, w_pf, hh, hl);

    // 10) gate / up projections
    gemm_mma<0><<<dim3(16, I_DIM/256, 1), 256, GEMM_SMEM>>>(
        hh, hl, wgt_h, wgt_l, ga_, H_DIM, H_DIM, H_DIM, I_DIM, 0, 0, 0, 1);
    gemm_mma<0><<<dim3(16, I_DIM/256, 1), 256, GEMM_SMEM>>>(
        hh, hl, wut_h, wut_l, up_, H_DIM, H_DIM, H_DIM, I_DIM, 0, 0, 0, 1);

    // 11) gelu_tanh(gate) * up (-> hi/lo)
    gelumul_split_kernel<<<4096, 256>>>(ga_, up_, guh, gul, S_LEN * I_DIM);

    // 12) down projection
    gemm_mma<0><<<dim3(16, H_DIM/256, 1), 256, GEMM_SMEM>>>(
        guh, gul, wdt_h, wdt_l, tm_, I_DIM, I_DIM, I_DIM, H_DIM, 0, 0, 0, 1);

    // 13) out = x1 + rms_norm(ff_out)
    add_rmsnorm_kernel<<<S_LEN, 256>>>(x1_, tm_, w_pff, (float*)d_out);

    (void)n_in; (void)out_size;
}

// round 5
// speedup vs baseline: 2.6457x; 1.0320x over previous
#include <cuda_runtime.h>
#include <cuda_bf16.h>
#include <math.h>
#include <stdint.h>

// ---------------------------------------------------------------------------
// Problem constants (Gemma2 decoder layer)
// ---------------------------------------------------------------------------
#define S_LEN   2048
#define H_DIM   3584
#define NH      16
#define NKV     8
#define HD      256
#define NQD     (NH * HD)     // 4096
#define NKVD    (NKV * HD)    // 2048
#define QKVD    (NQD + 2 * NKVD)  // 8192
#define I_DIM   14336
#define GUD     (2 * I_DIM)   // 28672
#define SCALE_F 0.0625f
#define SOFTCAP 50.0f
#define EPS_F   1e-6f

typedef __nv_bfloat16 bf16;

// ---------------------------------------------------------------------------
// Device scratch (static; runtime allocation is forbidden)
// ---------------------------------------------------------------------------
__device__ float g_qkv [(size_t)S_LEN * QKVD];        // fused QKV output
__device__ float g_sc  [(size_t)NH * S_LEN * S_LEN];  // scores
__device__ float g_tmp [(size_t)S_LEN * H_DIM];
__device__ float g_x1  [(size_t)S_LEN * H_DIM];
__device__ float g_gu  [(size_t)S_LEN * GUD];         // fused gate|up output

__device__ bf16 s_wqkvt_h[(size_t)QKVD * H_DIM], s_wqkvt_l[(size_t)QKVD * H_DIM];
__device__ bf16 s_wot_h [(size_t)H_DIM * NQD],   s_wot_l [(size_t)H_DIM * NQD];
__device__ bf16 s_wgut_h[(size_t)GUD * H_DIM],   s_wgut_l[(size_t)GUD * H_DIM];
__device__ bf16 s_wdt_h [(size_t)H_DIM * I_DIM], s_wdt_l [(size_t)H_DIM * I_DIM];
__device__ bf16 s_hh[(size_t)S_LEN * H_DIM],   s_hl[(size_t)S_LEN * H_DIM];
__device__ bf16 s_qh[(size_t)S_LEN * NQD],     s_ql[(size_t)S_LEN * NQD];
__device__ bf16 s_kh[(size_t)S_LEN * NKVD],    s_kl[(size_t)S_LEN * NKVD];
__device__ bf16 s_vth[(size_t)NKVD * S_LEN],   s_vtl[(size_t)NKVD * S_LEN];
__device__ bf16 s_ph[(size_t)NH * S_LEN * S_LEN], s_pl[(size_t)NH * S_LEN * S_LEN];
__device__ bf16 s_ath[(size_t)S_LEN * NQD],    s_atl[(size_t)S_LEN * NQD];
__device__ bf16 s_guh[(size_t)S_LEN * I_DIM],  s_gul[(size_t)S_LEN * I_DIM];

// ---------------------------------------------------------------------------
// helpers
// ---------------------------------------------------------------------------
__device__ __forceinline__ void bsplit(float x, bf16& h, bf16& l) {
    h = __float2bfloat16_rn(x);
    l = __float2bfloat16_rn(x - __bfloat162float(h));
}
__device__ __forceinline__ uint32_t packbf(bf16 a, bf16 b) {
    __nv_bfloat162 t(a, b);     // a = low half
    return *reinterpret_cast<uint32_t*>(&t);
}

template<bool IS_MAX>
__device__ __forceinline__ float block_reduce(float v) {
    __shared__ float sh[8];
    __syncthreads();
    int lane = threadIdx.x & 31, wid = threadIdx.x >> 5;
    #pragma unroll
    for (int o = 16; o; o >>= 1) {
        float t = __shfl_xor_sync(0xffffffffu, v, o);
        v = IS_MAX ? fmaxf(v, t) : (v + t);
    }
    if (lane == 0) sh[wid] = v;
    __syncthreads();
    if (wid == 0) {
        float r = (threadIdx.x < 8) ? sh[threadIdx.x] : (IS_MAX ? -3.4e38f : 0.0f);
        #pragma unroll
        for (int o = 4; o; o >>= 1) {
            float t = __shfl_xor_sync(0xffffffffu, r, o);
            r = IS_MAX ? fmaxf(r, t) : (r + t);
        }
        if (lane == 0) sh[0] = r;
    }
    __syncthreads();
    return sh[0];
}

__device__ __forceinline__ uint32_t smem_u32(const void* p) {
    uint32_t a;
    asm("{ .reg .u64 t; cvta.to.shared.u64 t, %1; cvt.u32.u64 %0, t; }" : "=r"(a) : "l"(p));
    return a;
}

#define CP16(dst, src) \
    asm volatile("cp.async.cg.shared.global [%0], [%1], 16;" \
                 :: "r"(dst), "l"(__cvta_generic_to_global(src)))
#define CP_COMMIT() asm volatile("cp.async.commit_group;" ::: "memory")
#define CP_WAIT2()  asm volatile("cp.async.wait_group 2;" ::: "memory")

__device__ __forceinline__ void mma_bf16(float* c, const uint32_t* a, const uint32_t* b) {
    asm volatile(
        "mma.sync.aligned.m16n8k16.row.col.f32.bf16.bf16.f32 "
        "{%0,%1,%2,%3}, {%4,%5,%6,%7}, {%8,%9}, {%0,%1,%2,%3};\n"
        : "+f"(c[0]), "+f"(c[1]), "+f"(c[2]), "+f"(c[3])
        : "r"(a[0]), "r"(a[1]), "r"(a[2]), "r"(a[3]), "r"(b[0]), "r"(b[1]));
}
__device__ __forceinline__ void ldsm4(uint32_t* r, uint32_t addr) {
    asm volatile("ldmatrix.sync.aligned.m8n8.x4.shared.b16 {%0,%1,%2,%3}, [%4];"
                 : "=r"(r[0]), "=r"(r[1]), "=r"(r[2]), "=r"(r[3]) : "r"(addr));
}

// ---------------------------------------------------------------------------
// mma.sync GEMM:  C[M, N] = A[M, K] * B[N, K]^T   (A,B bf16 hi/lo; C fp32 or
// split bf16 when OUT=1). CTA tile 128x256x32, 8 warps (2M x 4N) of 64x64.
// cp.async 3-stage pipeline; ldmatrix fragment loads; product-major MMA order.
// CMODE 0 plain; 1 causal tile skip; 2 K clipped to brow*128+128.
// grid = (M/128 [fast], N/256, Z).
// ---------------------------------------------------------------------------
#define STG_BYTES 49152          // A 16KB + B 32KB
#define GEMM_SMEM (3 * STG_BYTES)

template<int CMODE, int OUT>
__global__ void __launch_bounds__(256, 1)
gemm_mma(const bf16* __restrict__ Agh, const bf16* __restrict__ Agl,
         const bf16* __restrict__ Bgh, const bf16* __restrict__ Bgl,
         float* __restrict__ C, bf16* __restrict__ Ch, bf16* __restrict__ Cl,
         int K, int lda, int ldb, int ldc,
         long long sA, long long sB, long long sC, int zdivB)
{
    const int brow = blockIdx.x, bcol = blockIdx.y, bz = blockIdx.z;
    if (CMODE == 1 && 2 * bcol > brow) return;

    Agh += (long long)bz * sA;  Agl += (long long)bz * sA;
    Bgh += (long long)(bz / zdivB) * sB;  Bgl += (long long)(bz / zdivB) * sB;

    int kEnd = K;
    if (CMODE == 2) kEnd = min(K, brow * 128 + 128);
    const int nk = kEnd >> 5;

    extern __shared__ char smem[];
    const uint32_t smb = smem_u32(smem);

    const int tid  = threadIdx.x;
    const int lane = tid & 31;
    const int wid  = tid >> 5;
    const int warp_m = (wid & 1) * 64;
    const int warp_n = (wid >> 1) * 64;

    // ---- fragment smem offsets (relative to plane base) ----
    const int bsel = lane >> 3, jj = lane & 7;
    uint32_t aoff[4], boff[2][2];
    #pragma unroll
    for (int mi = 0; mi < 4; mi++) {
        const int r = warp_m + mi * 16 + (bsel & 1) * 8 + jj;
        const int c = bsel >> 1;
        aoff[mi] = r * 32 + ((c ^ ((r >> 2) & 1)) << 4);
    }
    #pragma unroll
    for (int ng = 0; ng < 2; ng++)
        #pragma unroll
        for (int q = 0; q < 2; q++) {
            const int r = warp_n + ng * 32 + q * 16 + (bsel >> 1) * 8 + jj;
            const int c = bsel & 1;
            boff[ng][q] = r * 32 + ((c ^ ((r >> 2) & 1)) << 4);
        }

    // ---- stage loader (cp.async) ----
    auto load_stage = [&](int kt, int buf) {
        const uint32_t sb = smb + buf * STG_BYTES;
        const int k0 = kt << 5;
        #pragma unroll
        for (int it = 0; it < 2; it++) {            // A: 512 chunks
            const int idx = tid + it * 256;
            const int r = idx >> 2, q = idx & 3, h = q >> 1, cg = q & 1;
            const int cs = cg ^ ((r >> 2) & 1);
            const uint32_t d = sb + h * 8192 + r * 32 + cs * 16;
            const long long g = (long long)(brow * 128 + r) * lda + k0 + h * 16 + cg * 8;
            CP16(d,        Agh + g);
            CP16(d + 4096, Agl + g);
        }
        #pragma unroll
        for (int it = 0; it < 4; it++) {            // B: 1024 chunks
            const int idx = tid + it * 256;
            const int r = idx >> 2, q = idx & 3, h = q >> 1, cg = q & 1;
            const int cs = cg ^ ((r >> 2) & 1);
            const uint32_t d = sb + 16384 + h * 16384 + r * 32 + cs * 16;
            const long long g = (long long)(bcol * 256 + r) * ldb + k0 + h * 16 + cg * 8;
            CP16(d,        Bgh + g);
            CP16(d + 8192, Bgl + g);
        }
    };

    float acc[4][8][4];
    #pragma unroll
    for (int mi = 0; mi < 4; mi++)
        #pragma unroll
        for (int ni = 0; ni < 8; ni++)
            #pragma unroll
            for (int r = 0; r < 4; r++) acc[mi][ni][r] = 0.0f;

    auto compute_stage = [&](int buf) {
        const uint32_t sb = smb + buf * STG_BYTES;
        #pragma unroll
        for (int h = 0; h < 2; h++) {               // two k16 halves
            const uint32_t aph = sb + h * 8192;
            const uint32_t apl = aph + 4096;
            const uint32_t bph = sb + 16384 + h * 16384;
            const uint32_t bpl = bph + 8192;

            uint32_t ah[4][4], al[4][4];
            #pragma unroll
            for (int mi = 0; mi < 4; mi++) {
                ldsm4(ah[mi], aph + aoff[mi]);
                ldsm4(al[mi], apl + aoff[mi]);
            }
            #pragma unroll
            for (int ng = 0; ng < 2; ng++) {
                uint32_t bh[4][2], bl[4][2];
                #pragma unroll
                for (int q = 0; q < 2; q++) {
                    uint32_t r[4];
                    ldsm4(r, bph + boff[ng][q]);
                    bh[2*q][0] = r[0]; bh[2*q][1] = r[1];
                    bh[2*q+1][0] = r[2]; bh[2*q+1][1] = r[3];
                    ldsm4(r, bpl + boff[ng][q]);
                    bl[2*q][0] = r[0]; bl[2*q][1] = r[1];
                    bl[2*q+1][0] = r[2]; bl[2*q+1][1] = r[3];
                }
                // product-major: acc reuse distance = 16 MMAs
                #pragma unroll
                for (int ni = 0; ni < 4; ni++)
                    #pragma unroll
                    for (int mi = 0; mi < 4; mi++)
                        mma_bf16(acc[mi][ng*4+ni], ah[mi], bh[ni]);
                #pragma unroll
                for (int ni = 0; ni < 4; ni++)
                    #pragma unroll
                    for (int mi = 0; mi < 4; mi++)
                        mma_bf16(acc[mi][ng*4+ni], al[mi], bh[ni]);
                #pragma unroll
                for (int ni = 0; ni < 4; ni++)
                    #pragma unroll
                    for (int mi = 0; mi < 4; mi++)
                        mma_bf16(acc[mi][ng*4+ni], ah[mi], bl[ni]);
            }
        }
    };

    // ---- 3-stage pipeline ----
    {
        int s = 0;
        for (; s < 3 && s < nk; s++) { load_stage(s, s); CP_COMMIT(); }
        for (; s < 3; s++) CP_COMMIT();
    }
    for (int kt = 0; kt < nk; kt++) {
        CP_WAIT2();
        __syncthreads();
        compute_stage(kt % 3);
        __syncthreads();
        if (kt + 3 < nk) load_stage(kt + 3, kt % 3);
        CP_COMMIT();
    }

    // ---- epilogue ----
    const int fr = lane >> 2, fc = (lane & 3) * 2;
    #pragma unroll
    for (int mi = 0; mi < 4; mi++) {
        const long long row = (long long)(brow * 128 + warp_m + mi * 16 + fr);
        #pragma unroll
        for (int ni = 0; ni < 8; ni++) {
            const long long col = (long long)(bcol * 256 + warp_n + ni * 8 + fc);
            if (OUT == 0) {
                float* c0 = C + (long long)bz * sC + row * ldc + col;
                float* c1 = C + (long long)bz * sC + (row + 8) * ldc + col;
                *(float2*)c0 = make_float2(acc[mi][ni][0], acc[mi][ni][1]);
                *(float2*)c1 = make_float2(acc[mi][ni][2], acc[mi][ni][3]);
            } else {
                bf16 h0,l0,h1,l1,h2,l2,h3,l3;
                bsplit(acc[mi][ni][0], h0, l0); bsplit(acc[mi][ni][1], h1, l1);
                bsplit(acc[mi][ni][2], h2, l2); bsplit(acc[mi][ni][3], h3, l3);
                bf16* ch0 = Ch + (long long)bz * sC + row * ldc + col;
                bf16* cl0 = Cl + (long long)bz * sC + row * ldc + col;
                bf16* ch1 = Ch + (long long)bz * sC + (row + 8) * ldc + col;
                bf16* cl1 = Cl + (long long)bz * sC + (row + 8) * ldc + col;
                *(uint32_t*)ch0 = packbf(h0, h1); *(uint32_t*)cl0 = packbf(l0, l1);
                *(uint32_t*)ch1 = packbf(h2, h3); *(uint32_t*)cl1 = packbf(l2, l3);
            }
        }
    }
}

// ---------------------------------------------------------------------------
// Transpose + split:  W[Kd, Nd] fp32 (row stride ldw)  ->  T[Nd, Kd] bf16 hi/lo
// ---------------------------------------------------------------------------
__global__ void tsplit_kernel(const float* __restrict__ W,
                              bf16* __restrict__ Th, bf16* __restrict__ Tl,
                              int Kd, int Nd, int ldw)
{
    __shared__ float t[32][33];
    const int n0 = blockIdx.x * 32, k0 = blockIdx.y * 32;
    const int tx = threadIdx.x, ty = threadIdx.y;
    #pragma unroll
    for (int i = 0; i < 4; i++)
        t[ty + i * 8][tx] = W[(long long)(k0 + ty + i * 8) * ldw + n0 + tx];
    __syncthreads();
    #pragma unroll
    for (int i = 0; i < 4; i++) {
        const float v = t[tx][ty + i * 8];
        bf16 h, l; bsplit(v, h, l);
        const long long o = (long long)(n0 + ty + i * 8) * Kd + k0 + tx;
        Th[o] = h; Tl[o] = l;
    }
}

// ---------------------------------------------------------------------------
// RMSNorm variants
// ---------------------------------------------------------------------------
__global__ void rmsnorm_split_kernel(const float* __restrict__ x,
                                     const float* __restrict__ w,
                                     bf16* __restrict__ oh, bf16* __restrict__ ol)
{
    const size_t base = (size_t)blockIdx.x * H_DIM;
    float ss = 0.0f;
    for (int j = threadIdx.x; j < H_DIM; j += blockDim.x) {
        float v = x[base + j]; ss += v * v;
    }
    ss = block_reduce<false>(ss);
    const float inv = rsqrtf(ss / (float)H_DIM + EPS_F);
    for (int j = threadIdx.x; j < H_DIM; j += blockDim.x) {
        bf16 h, l; bsplit(x[base + j] * inv * w[j], h, l);
        oh[base + j] = h; ol[base + j] = l;
    }
}

__global__ void add_rmsnorm_kernel(const float* __restrict__ resid,
                                   const float* __restrict__ t,
                                   const float* __restrict__ w,
                                   float* __restrict__ out)
{
    const size_t base = (size_t)blockIdx.x * H_DIM;
    float ss = 0.0f;
    for (int j = threadIdx.x; j < H_DIM; j += blockDim.x) {
        float v = t[base + j]; ss += v * v;
    }
    ss = block_reduce<false>(ss);
    const float inv = rsqrtf(ss / (float)H_DIM + EPS_F);
    for (int j = threadIdx.x; j < H_DIM; j += blockDim.x)
        out[base + j] = resid[base + j] + t[base + j] * inv * w[j];
}

// ---------------------------------------------------------------------------
// RoPE + split from fused QKV buffer (positions = arange(S))
// ---------------------------------------------------------------------------
__global__ void rope_split_kernel(const float* __restrict__ qkv,
                                  bf16* __restrict__ qh, bf16* __restrict__ ql,
                                  bf16* __restrict__ kh, bf16* __restrict__ kl)
{
    const int p = blockIdx.x;
    const int total = (NH + NKV) * 128;
    for (int t = threadIdx.x; t < total; t += blockDim.x) {
        const int d = t & 127;
        const float inv = powf(10000.0f, -(float)d * (1.0f / 128.0f));
        float sn, cs; sincosf((float)p * inv, &sn, &cs);
        size_t sbase, dbase;
        bf16 *dh, *dl;
        if (t < NH * 128) {
            const int head = t >> 7;
            sbase = (size_t)p * QKVD + head * HD + d;
            dbase = (size_t)p * NQD + head * HD + d;
            dh = qh; dl = ql;
        } else {
            const int head = (t - NH * 128) >> 7;
            sbase = (size_t)p * QKVD + NQD + head * HD + d;
            dbase = (size_t)p * NKVD + head * HD + d;
            dh = kh; dl = kl;
        }
        const float a = qkv[sbase], b = qkv[sbase + 128];
        bf16 h, l;
        bsplit(a * cs - b * sn, h, l); dh[dbase] = h;       dl[dbase] = l;
        bsplit(b * cs + a * sn, h, l); dh[dbase + 128] = h; dl[dbase + 128] = l;
    }
}

// ---------------------------------------------------------------------------
// Softcap + causal softmax -> probs bf16 hi/lo. No max pass (|logit| <= 50).
// ---------------------------------------------------------------------------
__global__ void softmax_split_kernel(float* __restrict__ sc,
                                     bf16* __restrict__ ph, bf16* __restrict__ pl)
{
    const int i = blockIdx.x, h = blockIdx.y;
    const size_t base = ((size_t)h * S_LEN + i) * S_LEN;
    float* row = sc + base;
    const int n = i + 1;

    float sm = 0.0f;
    for (int j = threadIdx.x; j < n; j += blockDim.x) {
        // cap = SOFTCAP * tanh(s*SCALE/SOFTCAP); tanh(z) = 1 - 2/(exp(2z)+1)
        const float e = __expf(row[j] * (SCALE_F * 2.0f / SOFTCAP));
        const float cap = SOFTCAP * (1.0f - __fdividef(2.0f, e + 1.0f));
        const float p = __expf(cap);     // cap in [-50,50]: exp is fp32-safe
        row[j] = p;
        sm += p;
    }
    sm = block_reduce<false>(sm);
    const float invs = 1.0f / sm;

    for (int j = threadIdx.x; j < n; j += blockDim.x) {
        bf16 hh, ll; bsplit(row[j] * invs, hh, ll);
        ph[base + j] = hh; pl[base + j] = ll;
    }
    const bf16 z = __float2bfloat16(0.0f);
    for (int j = n + threadIdx.x; j < S_LEN; j += blockDim.x) {
        ph[base + j] = z; pl[base + j] = z;
    }
}

// ---------------------------------------------------------------------------
// gelu_tanh(gate) * up -> split (reads fused [2048, 28672] buffer, float4)
// ---------------------------------------------------------------------------
__global__ void gelumul_split_kernel(const float* __restrict__ gu,
                                     bf16* __restrict__ oh, bf16* __restrict__ ol)
{
    const int row = blockIdx.y;
    const int col = (blockIdx.x * blockDim.x + threadIdx.x) * 4;
    const float4 g4 = *(const float4*)(gu + (size_t)row * GUD + col);
    const float4 u4 = *(const float4*)(gu + (size_t)row * GUD + I_DIM + col);
    const float* gp = &g4.x; const float* up = &u4.x;
    bf16 h[4], l[4];
    #pragma unroll
    for (int t = 0; t < 4; t++) {
        const float xv = gp[t];
        const float inner = 0.7978845608028654f * (xv + 0.044715f * xv * xv * xv);
        const float r = 0.5f * xv * (1.0f + tanhf(inner)) * up[t];
        bsplit(r, h[t], l[t]);
    }
    const size_t o = (size_t)row * I_DIM + col;
    *(uint2*)(oh + o) = make_uint2(packbf(h[0], h[1]), packbf(h[2], h[3]));
    *(uint2*)(ol + o) = make_uint2(packbf(l[0], l[1]), packbf(l[2], l[3]));
}

// ---------------------------------------------------------------------------
// Host launcher
// ---------------------------------------------------------------------------
#define SYM(v, s) do { cudaGetSymbolAddress((void**)&(v), s); } while (0)

extern "C" void kernel_launch(void* const* d_in, const int* in_sizes, int n_in,
                              void* d_out, int out_size)
{
    const float *x = nullptr, *w_in = nullptr, *w_pa = nullptr, *w_pf = nullptr,
                *w_pff = nullptr, *wq = nullptr, *wk = nullptr, *wv = nullptr,
                *wo = nullptr, *wg = nullptr, *wu = nullptr, *wd = nullptr;
    int c7 = 0, c14 = 0, c3584 = 0, c51 = 0;
    for (int i = 0; i < n_in; i++) {
        const int s = in_sizes[i];
        const float* p = (const float*)d_in[i];
        if (s == S_LEN * H_DIM) {
            if (c7 == 0) x = p; else if (c7 == 1) wk = p; else wv = p;
            c7++;
        } else if (s == H_DIM * NQD) {
            if (c14 == 0) wq = p; else wo = p;
            c14++;
        } else if (s == H_DIM) {
            if (c3584 == 0) w_in = p; else if (c3584 == 1) w_pa = p;
            else if (c3584 == 2) w_pf = p; else w_pff = p;
            c3584++;
        } else if (s == H_DIM * I_DIM) {
            if (c51 == 0) wg = p; else if (c51 == 1) wu = p; else wd = p;
            c51++;
        }
    }

    float *qkv_, *sc_, *tm_, *x1_, *gu_;
    SYM(qkv_, g_qkv); SYM(sc_, g_sc); SYM(tm_, g_tmp); SYM(x1_, g_x1); SYM(gu_, g_gu);

    bf16 *wqkvt_h, *wqkvt_l, *wot_h, *wot_l, *wgut_h, *wgut_l, *wdt_h, *wdt_l;
    bf16 *hh, *hl, *qh, *ql, *kh, *kl, *vth, *vtl, *ph, *pl, *ath, *atl, *guh, *gul;
    SYM(wqkvt_h, s_wqkvt_h); SYM(wqkvt_l, s_wqkvt_l);
    SYM(wot_h, s_wot_h); SYM(wot_l, s_wot_l);
    SYM(wgut_h, s_wgut_h); SYM(wgut_l, s_wgut_l);
    SYM(wdt_h, s_wdt_h); SYM(wdt_l, s_wdt_l);
    SYM(hh, s_hh); SYM(hl, s_hl); SYM(qh, s_qh); SYM(ql, s_ql);
    SYM(kh, s_kh); SYM(kl, s_kl); SYM(vth, s_vth); SYM(vtl, s_vtl);
    SYM(ph, s_ph); SYM(pl, s_pl); SYM(ath, s_ath); SYM(atl, s_atl);
    SYM(guh, s_guh); SYM(gul, s_gul);

    cudaFuncSetAttribute(gemm_mma<0,0>, cudaFuncAttributeMaxDynamicSharedMemorySize, GEMM_SMEM);
    cudaFuncSetAttribute(gemm_mma<1,0>, cudaFuncAttributeMaxDynamicSharedMemorySize, GEMM_SMEM);
    cudaFuncSetAttribute(gemm_mma<2,1>, cudaFuncAttributeMaxDynamicSharedMemorySize, GEMM_SMEM);

    const dim3 tb(32, 8);
    const long long SS = (long long)S_LEN * S_LEN;
    const long long KO = (long long)H_DIM;   // common transposed weight ld

    // ---- weight transpose + split (fused destinations) ----
    tsplit_kernel<<<dim3(NQD/32,  H_DIM/32), tb>>>(wq, wqkvt_h, wqkvt_l, H_DIM, NQD, NQD);
    tsplit_kernel<<<dim3(NKVD/32, H_DIM/32), tb>>>(wk, wqkvt_h + (size_t)NQD*KO,
                                                   wqkvt_l + (size_t)NQD*KO, H_DIM, NKVD, NKVD);
    tsplit_kernel<<<dim3(NKVD/32, H_DIM/32), tb>>>(wv, wqkvt_h + (size_t)(NQD+NKVD)*KO,
                                                   wqkvt_l + (size_t)(NQD+NKVD)*KO, H_DIM, NKVD, NKVD);
    tsplit_kernel<<<dim3(H_DIM/32, NQD/32),  tb>>>(wo, wot_h, wot_l, NQD, H_DIM, H_DIM);
    tsplit_kernel<<<dim3(I_DIM/32, H_DIM/32), tb>>>(wg, wgut_h, wgut_l, H_DIM, I_DIM, I_DIM);
    tsplit_kernel<<<dim3(I_DIM/32, H_DIM/32), tb>>>(wu, wgut_h + (size_t)I_DIM*KO,
                                                    wgut_l + (size_t)I_DIM*KO, H_DIM, I_DIM, I_DIM);
    tsplit_kernel<<<dim3(H_DIM/32, I_DIM/32), tb>>>(wd, wdt_h, wdt_l, I_DIM, H_DIM, H_DIM);

    // 1) pre-attn norm (-> hi/lo)
    rmsnorm_split_kernel<<<S_LEN, 256>>>(x, w_in, hh, hl);

    // 2) fused QKV projection (N = 8192)
    gemm_mma<0,0><<<dim3(16, QKVD/256, 1), 256, GEMM_SMEM>>>(
        hh, hl, wqkvt_h, wqkvt_l, qkv_, nullptr, nullptr,
        H_DIM, H_DIM, H_DIM, QKVD, 0, 0, 0, 1);

    // 3) RoPE (+split); V transpose (+split) straight out of qkv
    rope_split_kernel<<<S_LEN, 256>>>(qkv_, qh, ql, kh, kl);
    tsplit_kernel<<<dim3(NKVD/32, S_LEN/32), tb>>>(qkv_ + NQD + NKVD, vth, vtl,
                                                   S_LEN, NKVD, QKVD);

    // 4) scores = Q K^T per head (causal tile skip)
    gemm_mma<1,0><<<dim3(16, S_LEN/256, NH), 256, GEMM_SMEM>>>(
        qh, ql, kh, kl, sc_, nullptr, nullptr,
        HD, NQD, NKVD, S_LEN, (long long)HD, (long long)HD, SS, 2);

    // 5) softcap + softmax (-> probs hi/lo)
    softmax_split_kernel<<<dim3(S_LEN, NH), 256>>>(sc_, ph, pl);

    // 6) attn = P @ V per head (K clipped, split output)
    gemm_mma<2,1><<<dim3(16, 1, NH), 256, GEMM_SMEM>>>(
        ph, pl, vth, vtl, nullptr, ath, atl,
        S_LEN, S_LEN, S_LEN, NQD, SS, (long long)HD * S_LEN, (long long)HD, 2);

    // 7) output projection
    gemm_mma<0,0><<<dim3(16, H_DIM/256, 1), 256, GEMM_SMEM>>>(
        ath, atl, wot_h, wot_l, tm_, nullptr, nullptr,
        NQD, NQD, NQD, H_DIM, 0, 0, 0, 1);

    // 8) x1 = x + rms_norm(attn_out)
    add_rmsnorm_kernel<<<S_LEN, 256>>>(x, tm_, w_pa, x1_);

    // 9) pre-FF norm (-> hi/lo)
    rmsnorm_split_kernel<<<S_LEN, 256>>>(x1_, w_pf, hh, hl);

    // 10) fused gate|up projection (N = 28672)
    gemm_mma<0,0><<<dim3(16, GUD/256, 1), 256, GEMM_SMEM>>>(
        hh, hl, wgut_h, wgut_l, gu_, nullptr, nullptr,
        H_DIM, H_DIM, H_DIM, GUD, 0, 0, 0, 1);

    // 11) gelu_tanh(gate) * up (-> hi/lo)
    gelumul_split_kernel<<<dim3(I_DIM/(256*4), S_LEN), 256>>>(gu_, guh, gul);

    // 12) down projection
    gemm_mma<0,0><<<dim3(16, H_DIM/256, 1), 256, GEMM_SMEM>>>(
        guh, gul, wdt_h, wdt_l, tm_, nullptr, nullptr,
        I_DIM, I_DIM, I_DIM, H_DIM, 0, 0, 0, 1);

    // 13) out = x1 + rms_norm(ff_out)
    add_rmsnorm_kernel<<<S_LEN, 256>>>(x1_, tm_, w_pff, (float*)d_out);

    (void)n_in; (void)out_size;
}

// round 10
// speedup vs baseline: 3.6842x; 1.3925x over previous
#include <cuda_runtime.h>
#include <cuda_bf16.h>
#include <math.h>
#include <stdint.h>

// ---------------------------------------------------------------------------
// Problem constants (Gemma2 decoder layer)
// ---------------------------------------------------------------------------
#define S_LEN   2048
#define H_DIM   3584
#define NH      16
#define NKV     8
#define HD      256
#define NQD     (NH * HD)         // 4096
#define NKVD    (NKV * HD)        // 2048
#define QKVD    (NQD + 2 * NKVD)  // 8192
#define I_DIM   14336
#define GUD     (2 * I_DIM)       // 28672
#define SCALE_F 0.0625f
#define SOFTCAP 50.0f
#define EPS_F   1e-6f

typedef __nv_bfloat16 bf16;

// ---------------------------------------------------------------------------
// Tiled operand layout: matrix [R, K] (bf16 hi/lo) stored as 16KB tiles.
// tile (rt = r/128, kt = k/32), ktn = K/32 tiles per row-band.
// tile bytes: [hi: h0 4KB | h1 4KB | lo: h0 4KB | h1 4KB], h = k16 half.
// ---------------------------------------------------------------------------
__device__ __forceinline__ size_t tile_off(int r, int k, int ktn) {
    size_t t = (size_t)(r >> 7) * ktn + (k >> 5);
    int rr = r & 127, cc = k & 31;
    return t * 16384 + (size_t)((cc >> 4) * 4096 + rr * 32
         + ((((cc >> 3) & 1) ^ ((rr >> 2) & 1)) << 4) + (cc & 7) * 2);
}

// ---------------------------------------------------------------------------
// Device scratch (static; runtime allocation is forbidden)
// ---------------------------------------------------------------------------
__device__ float g_qkv [(size_t)S_LEN * QKVD];
__device__ float g_sc  [(size_t)NH * S_LEN * S_LEN];
__device__ float g_tmp [(size_t)S_LEN * H_DIM];
__device__ float g_x1  [(size_t)S_LEN * H_DIM];
__device__ float g_gu  [(size_t)S_LEN * GUD];

#define TBUF(name, R, K) __device__ __align__(16384) char name[(size_t)(R) * (K) * 4]
TBUF(c_wqkvt, QKVD, H_DIM);
TBUF(c_wot,  H_DIM, NQD);
TBUF(c_wgut, GUD,  H_DIM);
TBUF(c_wdt,  H_DIM, I_DIM);
TBUF(c_h,    S_LEN, H_DIM);
TBUF(c_q,    S_LEN, NQD);
TBUF(c_k,    S_LEN, NKVD);
TBUF(c_vt,   NKVD, S_LEN);
TBUF(c_p,    (size_t)NH * S_LEN, S_LEN);
TBUF(c_at,   S_LEN, NQD);
TBUF(c_gu,   S_LEN, I_DIM);

// ---------------------------------------------------------------------------
// helpers
// ---------------------------------------------------------------------------
__device__ __forceinline__ void bsplit(float x, bf16& h, bf16& l) {
    h = __float2bfloat16_rn(x);
    l = __float2bfloat16_rn(x - __bfloat162float(h));
}
__device__ __forceinline__ uint32_t packbf(bf16 a, bf16 b) {
    __nv_bfloat162 t(a, b);
    return *reinterpret_cast<uint32_t*>(&t);
}

template<bool IS_MAX>
__device__ __forceinline__ float block_reduce(float v) {
    __shared__ float sh[8];
    __syncthreads();
    int lane = threadIdx.x & 31, wid = threadIdx.x >> 5;
    #pragma unroll
    for (int o = 16; o; o >>= 1) {
        float t = __shfl_xor_sync(0xffffffffu, v, o);
        v = IS_MAX ? fmaxf(v, t) : (v + t);
    }
    if (lane == 0) sh[wid] = v;
    __syncthreads();
    if (wid == 0) {
        float r = (threadIdx.x < 8) ? sh[threadIdx.x] : (IS_MAX ? -3.4e38f : 0.0f);
        #pragma unroll
        for (int o = 4; o; o >>= 1) {
            float t = __shfl_xor_sync(0xffffffffu, r, o);
            r = IS_MAX ? fmaxf(r, t) : (r + t);
        }
        if (lane == 0) sh[0] = r;
    }
    __syncthreads();
    return sh[0];
}

__device__ __forceinline__ uint32_t smem_u32(const void* p) {
    uint32_t a;
    asm("{ .reg .u64 t; cvta.to.shared.u64 t, %1; cvt.u32.u64 %0, t; }" : "=r"(a) : "l"(p));
    return a;
}

#define MBAR_INIT(a, cnt) asm volatile("mbarrier.init.shared.b64 [%0], %1;" :: "r"(a), "r"(cnt) : "memory")
#define MBAR_EXPECT_TX(a, n) asm volatile("mbarrier.arrive.expect_tx.shared.b64 _, [%0], %1;" :: "r"(a), "r"(n) : "memory")
#define MBAR_WAIT(a, ph)  do {                                                               \
    asm volatile("{\n .reg .pred P1;\n"                                                      \
                 "WL%=:\n mbarrier.try_wait.parity.acquire.cta.shared::cta.b64 P1,[%0],%1,0x989680;\n" \
                 "@P1 bra.uni WD%=;\n bra.uni WL%=;\nWD%=:\n}"                               \
                 :: "r"(a), "r"(ph) : "memory"); } while (0)
#define BULK_G2S(dst, src, n, bar) \
    asm volatile("cp.async.bulk.shared::cluster.global.mbarrier::complete_tx::bytes [%0], [%1], %2, [%3];" \
                 :: "r"(dst), "l"(__cvta_generic_to_global(src)), "r"(n), "r"(bar) : "memory")

__device__ __forceinline__ void mma_bf16(float* c, const uint32_t* a, const uint32_t* b) {
    asm volatile(
        "mma.sync.aligned.m16n8k16.row.col.f32.bf16.bf16.f32 "
        "{%0,%1,%2,%3}, {%4,%5,%6,%7}, {%8,%9}, {%0,%1,%2,%3};\n"
        : "+f"(c[0]), "+f"(c[1]), "+f"(c[2]), "+f"(c[3])
        : "r"(a[0]), "r"(a[1]), "r"(a[2]), "r"(a[3]), "r"(b[0]), "r"(b[1]));
}
__device__ __forceinline__ void ldsm4(uint32_t* r, uint32_t addr) {
    asm volatile("ldmatrix.sync.aligned.m8n8.x4.shared.b16 {%0,%1,%2,%3}, [%4];"
                 : "=r"(r[0]), "=r"(r[1]), "=r"(r[2]), "=r"(r[3]) : "r"(addr));
}

// ---------------------------------------------------------------------------
// mma.sync GEMM on pre-tiled operands:  C[M, N] = A[M, K] * B[N, K]^T
//   CTA tile 128x256x32, 8 warps (2M x 4N) of 64x64, split-bf16 3-product.
//   Stage feed = 3 cp.async.bulk (A tile + 2 B tiles = 48KB) + mbarrier tx.
//   4-stage ring. CMODE 0 plain; 1 causal skip; 2 K clip (brow*4+4 tiles).
//   OUT 0: fp32 row-major (+ bz*sC). OUT 1: tiled bf16 hi/lo (ldcT ktn).
// ---------------------------------------------------------------------------
#define STG_BYTES 49152
#define NSTG      4
#define GEMM_SMEM (1024 + NSTG * STG_BYTES)

template<int CMODE, int OUT>
__global__ void __launch_bounds__(256, 1)
gemm_mma(const char* __restrict__ At, const char* __restrict__ Bt,
         float* __restrict__ C, char* __restrict__ Ct,
         int nkTot, int ldaT, int ldbT, int ldcF, int ldcT, long long sC,
         long long sAT, long long sBT, int zdivB, int ccol)
{
    const int brow = blockIdx.x, bcol = blockIdx.y, bz = blockIdx.z;
    if (CMODE == 1 && 2 * bcol > brow) return;

    int nk = nkTot;
    if (CMODE == 2) nk = min(nkTot, brow * 4 + 4);

    const long long aBase = bz * sAT + (long long)brow * ldaT;
    const long long bT0 = (bz / zdivB) * sBT + (long long)(bcol * 2) * ldbT;
    const long long bT1 = bT0 + ldbT;

    extern __shared__ char smem[];
    const uint32_t smb = smem_u32(smem);

    const int tid  = threadIdx.x;
    const int lane = tid & 31;
    const int wid  = tid >> 5;
    const int warp_m = (wid & 1) * 64;
    const int warp_n = (wid >> 1) * 64;
    const uint32_t bbadd = 16384u + (uint32_t)(warp_n >> 7) * 16384u;

    if (tid == 0) {
        #pragma unroll
        for (int s = 0; s < NSTG; s++) MBAR_INIT(smb + 16 * s, 1);
    }
    asm volatile("fence.proxy.async.shared::cta;" ::: "memory");
    __syncthreads();

    // ---- fragment smem offsets (within a 4KB k16 plane) ----
    const int bsel = lane >> 3, jj = lane & 7;
    uint32_t aoff[4], boff[2][2];
    #pragma unroll
    for (int mi = 0; mi < 4; mi++) {
        const int r = warp_m + mi * 16 + (bsel & 1) * 8 + jj;
        const int c = bsel >> 1;
        aoff[mi] = r * 32 + ((c ^ ((r >> 2) & 1)) << 4);
    }
    #pragma unroll
    for (int ng = 0; ng < 2; ng++)
        #pragma unroll
        for (int q = 0; q < 2; q++) {
            const int r = (warp_n & 127) + ng * 32 + q * 16 + (bsel >> 1) * 8 + jj;
            const int c = bsel & 1;
            boff[ng][q] = r * 32 + ((c ^ ((r >> 2) & 1)) << 4);
        }

    auto fill = [&](int kt, int s) {   // thread 0 only
        const uint32_t bar = smb + 16 * s;
        const uint32_t sb = smb + 1024 + s * STG_BYTES;
        MBAR_EXPECT_TX(bar, (uint32_t)STG_BYTES);
        BULK_G2S(sb,          At + (aBase + kt) * 16384LL, 16384u, bar);
        BULK_G2S(sb + 16384u, Bt + (bT0 + kt) * 16384LL,   16384u, bar);
        BULK_G2S(sb + 32768u, Bt + (bT1 + kt) * 16384LL,   16384u, bar);
    };

    float acc[4][8][4];
    #pragma unroll
    for (int mi = 0; mi < 4; mi++)
        #pragma unroll
        for (int ni = 0; ni < 8; ni++)
            #pragma unroll
            for (int r = 0; r < 4; r++) acc[mi][ni][r] = 0.0f;

    auto compute_stage = [&](int s) {
        const uint32_t sb = smb + 1024 + s * STG_BYTES;
        #pragma unroll
        for (int h = 0; h < 2; h++) {
            const uint32_t aph = sb + h * 4096u;
            const uint32_t apl = aph + 8192u;
            const uint32_t bph = sb + bbadd + h * 4096u;
            const uint32_t bpl = bph + 8192u;

            uint32_t ah[4][4], al[4][4];
            #pragma unroll
            for (int mi = 0; mi < 4; mi++) {
                ldsm4(ah[mi], aph + aoff[mi]);
                ldsm4(al[mi], apl + aoff[mi]);
            }
            #pragma unroll
            for (int ng = 0; ng < 2; ng++) {
                uint32_t bh[4][2], bl[4][2];
                #pragma unroll
                for (int q = 0; q < 2; q++) {
                    uint32_t r[4];
                    ldsm4(r, bph + boff[ng][q]);
                    bh[2*q][0] = r[0]; bh[2*q][1] = r[1];
                    bh[2*q+1][0] = r[2]; bh[2*q+1][1] = r[3];
                    ldsm4(r, bpl + boff[ng][q]);
                    bl[2*q][0] = r[0]; bl[2*q][1] = r[1];
                    bl[2*q+1][0] = r[2]; bl[2*q+1][1] = r[3];
                }
                #pragma unroll
                for (int ni = 0; ni < 4; ni++)
                    #pragma unroll
                    for (int mi = 0; mi < 4; mi++)
                        mma_bf16(acc[mi][ng*4+ni], ah[mi], bh[ni]);
                #pragma unroll
                for (int ni = 0; ni < 4; ni++)
                    #pragma unroll
                    for (int mi = 0; mi < 4; mi++)
                        mma_bf16(acc[mi][ng*4+ni], al[mi], bh[ni]);
                #pragma unroll
                for (int ni = 0; ni < 4; ni++)
                    #pragma unroll
                    for (int mi = 0; mi < 4; mi++)
                        mma_bf16(acc[mi][ng*4+ni], ah[mi], bl[ni]);
            }
        }
    };

    if (tid == 0) {
        for (int s = 0; s < NSTG && s < nk; s++) fill(s, s);
    }
    for (int kt = 0; kt < nk; kt++) {
        const int s = kt & (NSTG - 1);
        const int m = kt >> 2;
        MBAR_WAIT(smb + 16 * s, m & 1);
        compute_stage(s);
        __syncthreads();
        if (tid == 0 && kt + NSTG < nk) fill(kt + NSTG, s);
    }

    // ---- epilogue ----
    const int fr = lane >> 2, fc = (lane & 3) * 2;
    #pragma unroll
    for (int mi = 0; mi < 4; mi++) {
        const int row = brow * 128 + warp_m + mi * 16 + fr;
        #pragma unroll
        for (int ni = 0; ni < 8; ni++) {
            const int col = bcol * 256 + bz * ccol + warp_n + ni * 8 + fc;
            if (OUT == 0) {
                float* c0 = C + bz * sC + (long long)row * ldcF + col;
                float* c1 = C + bz * sC + (long long)(row + 8) * ldcF + col;
                *(float2*)c0 = make_float2(acc[mi][ni][0], acc[mi][ni][1]);
                *(float2*)c1 = make_float2(acc[mi][ni][2], acc[mi][ni][3]);
            } else {
                bf16 h0,l0,h1,l1,h2,l2,h3,l3;
                bsplit(acc[mi][ni][0], h0, l0); bsplit(acc[mi][ni][1], h1, l1);
                bsplit(acc[mi][ni][2], h2, l2); bsplit(acc[mi][ni][3], h3, l3);
                size_t o0 = tile_off(row, col, ldcT);
                size_t o1 = tile_off(row + 8, col, ldcT);
                *(uint32_t*)(Ct + o0)        = packbf(h0, h1);
                *(uint32_t*)(Ct + o0 + 8192) = packbf(l0, l1);
                *(uint32_t*)(Ct + o1)        = packbf(h2, h3);
                *(uint32_t*)(Ct + o1 + 8192) = packbf(l2, l3);
            }
        }
    }
}

// ---------------------------------------------------------------------------
// Transpose + split + tile:  W[Kd, Nd] fp32 (row stride ldw) -> tiled T[Nd, Kd]
// ---------------------------------------------------------------------------
__global__ void tsplit_kernel(const float* __restrict__ W, char* __restrict__ T,
                              int Kd, int Nd, int ldw)
{
    __shared__ float t[32][33];
    const int n0 = blockIdx.x * 32, k0 = blockIdx.y * 32;
    const int tx = threadIdx.x, ty = threadIdx.y;
    const int ktn = Kd >> 5;
    #pragma unroll
    for (int i = 0; i < 4; i++)
        t[ty + i * 8][tx] = W[(long long)(k0 + ty + i * 8) * ldw + n0 + tx];
    __syncthreads();
    const int tid = ty * 32 + tx;
    if (tid < 128) {
        const int nn = tid >> 2, kq = (tid & 3) * 8;
        bf16 h[8], l[8];
        #pragma unroll
        for (int i = 0; i < 8; i++) bsplit(t[kq + i][nn], h[i], l[i]);
        const size_t off = tile_off(n0 + nn, k0 + kq, ktn);
        *(uint4*)(T + off) = make_uint4(packbf(h[0],h[1]), packbf(h[2],h[3]),
                                        packbf(h[4],h[5]), packbf(h[6],h[7]));
        *(uint4*)(T + off + 8192) = make_uint4(packbf(l[0],l[1]), packbf(l[2],l[3]),
                                               packbf(l[4],l[5]), packbf(l[6],l[7]));
    }
}

// ---------------------------------------------------------------------------
// RMSNorm -> tiled hi/lo
// ---------------------------------------------------------------------------
__global__ void rmsnorm_split_kernel(const float* __restrict__ x,
                                     const float* __restrict__ w,
                                     char* __restrict__ out)
{
    const int row = blockIdx.x;
    const size_t base = (size_t)row * H_DIM;
    float ss = 0.0f;
    for (int j = threadIdx.x; j < H_DIM; j += blockDim.x) {
        float v = x[base + j]; ss += v * v;
    }
    ss = block_reduce<false>(ss);
    const float inv = rsqrtf(ss / (float)H_DIM + EPS_F);
    for (int ch = threadIdx.x; ch < H_DIM / 8; ch += blockDim.x) {
        const int k0 = ch * 8;
        const float4 a = *(const float4*)(x + base + k0);
        const float4 b = *(const float4*)(x + base + k0 + 4);
        const float4 wa = *(const float4*)(w + k0);
        const float4 wb = *(const float4*)(w + k0 + 4);
        const float vv[8] = { a.x*inv*wa.x, a.y*inv*wa.y, a.z*inv*wa.z, a.w*inv*wa.w,
                              b.x*inv*wb.x, b.y*inv*wb.y, b.z*inv*wb.z, b.w*inv*wb.w };
        bf16 h[8], l[8];
        #pragma unroll
        for (int i = 0; i < 8; i++) bsplit(vv[i], h[i], l[i]);
        const size_t off = tile_off(row, k0, H_DIM / 32);
        *(uint4*)(out + off) = make_uint4(packbf(h[0],h[1]), packbf(h[2],h[3]),
                                          packbf(h[4],h[5]), packbf(h[6],h[7]));
        *(uint4*)(out + off + 8192) = make_uint4(packbf(l[0],l[1]), packbf(l[2],l[3]),
                                                 packbf(l[4],l[5]), packbf(l[6],l[7]));
    }
}

__global__ void add_rmsnorm_kernel(const float* __restrict__ resid,
                                   const float* __restrict__ t,
                                   const float* __restrict__ w,
                                   float* __restrict__ out)
{
    const size_t base = (size_t)blockIdx.x * H_DIM;
    float ss = 0.0f;
    for (int j = threadIdx.x; j < H_DIM; j += blockDim.x) {
        float v = t[base + j]; ss += v * v;
    }
    ss = block_reduce<false>(ss);
    const float inv = rsqrtf(ss / (float)H_DIM + EPS_F);
    for (int j = threadIdx.x; j < H_DIM; j += blockDim.x)
        out[base + j] = resid[base + j] + t[base + j] * inv * w[j];
}

// ---------------------------------------------------------------------------
// RoPE -> tiled Q (ktn=128) and K (ktn=64)
// ---------------------------------------------------------------------------
__global__ void rope_split_kernel(const float* __restrict__ qkv,
                                  char* __restrict__ qt, char* __restrict__ kt)
{
    const int p = blockIdx.x;
    const int total = (NH + NKV) * 128;
    for (int t = threadIdx.x; t < total; t += blockDim.x) {
        const int d = t & 127;
        const float inv = powf(10000.0f, -(float)d * (1.0f / 128.0f));
        float sn, cs; sincosf((float)p * inv, &sn, &cs);
        size_t sbase; int col; char* dst; int ktn;
        if (t < NH * 128) {
            const int head = t >> 7;
            sbase = (size_t)p * QKVD + head * HD + d;
            col = head * HD + d; dst = qt; ktn = NQD / 32;
        } else {
            const int head = (t - NH * 128) >> 7;
            sbase = (size_t)p * QKVD + NQD + head * HD + d;
            col = head * HD + d; dst = kt; ktn = NKVD / 32;
        }
        const float a = qkv[sbase], b = qkv[sbase + 128];
        bf16 h, l;
        size_t o = tile_off(p, col, ktn);
        bsplit(a * cs - b * sn, h, l);
        *(bf16*)(dst + o) = h; *(bf16*)(dst + o + 8192) = l;
        o = tile_off(p, col + 128, ktn);
        bsplit(b * cs + a * sn, h, l);
        *(bf16*)(dst + o) = h; *(bf16*)(dst + o + 8192) = l;
    }
}

// ---------------------------------------------------------------------------
// Softcap + causal softmax -> tiled P per head (ktn=64); tail zeroed
// ---------------------------------------------------------------------------
__global__ void softmax_split_kernel(float* __restrict__ sc, char* __restrict__ pt)
{
    const int i = blockIdx.x, h = blockIdx.y;
    const size_t base = ((size_t)h * S_LEN + i) * S_LEN;
    float* row = sc + base;
    char* ph = pt + (size_t)h * ((S_LEN / 128) * (S_LEN / 32) * 16384);
    const int n = i + 1;

    float sm = 0.0f;
    for (int j = threadIdx.x; j < n; j += blockDim.x) {
        const float e = __expf(row[j] * (SCALE_F * 2.0f / SOFTCAP));
        const float cap = SOFTCAP * (1.0f - __fdividef(2.0f, e + 1.0f));
        const float p = __expf(cap);
        row[j] = p;
        sm += p;
    }
    sm = block_reduce<false>(sm);
    const float invs = 1.0f / sm;

    for (int j = threadIdx.x; j < n; j += blockDim.x) {
        bf16 hh, ll; bsplit(row[j] * invs, hh, ll);
        const size_t o = tile_off(i, j, S_LEN / 32);
        *(bf16*)(ph + o) = hh; *(bf16*)(ph + o + 8192) = ll;
    }
    const bf16 z = __float2bfloat16(0.0f);
    for (int j = n + threadIdx.x; j < S_LEN; j += blockDim.x) {
        const size_t o = tile_off(i, j, S_LEN / 32);
        *(bf16*)(ph + o) = z; *(bf16*)(ph + o + 8192) = z;
    }
}

// ---------------------------------------------------------------------------
// gelu_tanh(gate) * up -> tiled hi/lo (ktn=448)
// ---------------------------------------------------------------------------
__global__ void gelumul_split_kernel(const float* __restrict__ gu, char* __restrict__ out)
{
    const int row = blockIdx.y;
    const int col = (blockIdx.x * blockDim.x + threadIdx.x) * 4;
    const float4 g4 = *(const float4*)(gu + (size_t)row * GUD + col);
    const float4 u4 = *(const float4*)(gu + (size_t)row * GUD + I_DIM + col);
    const float* gp = &g4.x; const float* up = &u4.x;
    bf16 h[4], l[4];
    #pragma unroll
    for (int t = 0; t < 4; t++) {
        const float xv = gp[t];
        const float inner = 0.7978845608028654f * (xv + 0.044715f * xv * xv * xv);
        const float r = 0.5f * xv * (1.0f + tanhf(inner)) * up[t];
        bsplit(r, h[t], l[t]);
    }
    const size_t off = tile_off(row, col, I_DIM / 32);
    *(uint2*)(out + off) = make_uint2(packbf(h[0], h[1]), packbf(h[2], h[3]));
    *(uint2*)(out + off + 8192) = make_uint2(packbf(l[0], l[1]), packbf(l[2], l[3]));
}

// ---------------------------------------------------------------------------
// Host launcher
// ---------------------------------------------------------------------------
#define SYM(v, s) do { cudaGetSymbolAddress((void**)&(v), s); } while (0)

extern "C" void kernel_launch(void* const* d_in, const int* in_sizes, int n_in,
                              void* d_out, int out_size)
{
    const float *x = nullptr, *w_in = nullptr, *w_pa = nullptr, *w_pf = nullptr,
                *w_pff = nullptr, *wq = nullptr, *wk = nullptr, *wv = nullptr,
                *wo = nullptr, *wg = nullptr, *wu = nullptr, *wd = nullptr;
    int c7 = 0, c14 = 0, c3584 = 0, c51 = 0;
    for (int i = 0; i < n_in; i++) {
        const int s = in_sizes[i];
        const float* p = (const float*)d_in[i];
        if (s == S_LEN * H_DIM) {
            if (c7 == 0) x = p; else if (c7 == 1) wk = p; else wv = p;
            c7++;
        } else if (s == H_DIM * NQD) {
            if (c14 == 0) wq = p; else wo = p;
            c14++;
        } else if (s == H_DIM) {
            if (c3584 == 0) w_in = p; else if (c3584 == 1) w_pa = p;
            else if (c3584 == 2) w_pf = p; else w_pff = p;
            c3584++;
        } else if (s == H_DIM * I_DIM) {
            if (c51 == 0) wg = p; else if (c51 == 1) wu = p; else wd = p;
            c51++;
        }
    }

    float *qkv_, *sc_, *tm_, *x1_, *gu_;
    SYM(qkv_, g_qkv); SYM(sc_, g_sc); SYM(tm_, g_tmp); SYM(x1_, g_x1); SYM(gu_, g_gu);
    char *wqkvt, *wot, *wgut, *wdt, *ht, *qt, *kt, *vt, *pt, *att, *gut;
    SYM(wqkvt, c_wqkvt); SYM(wot, c_wot); SYM(wgut, c_wgut); SYM(wdt, c_wdt);
    SYM(ht, c_h); SYM(qt, c_q); SYM(kt, c_k); SYM(vt, c_vt);
    SYM(pt, c_p); SYM(att, c_at); SYM(gut, c_gu);

    cudaFuncSetAttribute(gemm_mma<0,0>, cudaFuncAttributeMaxDynamicSharedMemorySize, GEMM_SMEM);
    cudaFuncSetAttribute(gemm_mma<1,0>, cudaFuncAttributeMaxDynamicSharedMemorySize, GEMM_SMEM);
    cudaFuncSetAttribute(gemm_mma<2,1>, cudaFuncAttributeMaxDynamicSharedMemorySize, GEMM_SMEM);

    const dim3 tb(32, 8);
    const long long SS = (long long)S_LEN * S_LEN;

    // ---- weight transpose + split + tile ----
    tsplit_kernel<<<dim3(NQD/32,  H_DIM/32), tb>>>(wq, wqkvt, H_DIM, NQD, NQD);
    tsplit_kernel<<<dim3(NKVD/32, H_DIM/32), tb>>>(wk, wqkvt + (size_t)(NQD>>7)*112*16384,
                                                   H_DIM, NKVD, NKVD);
    tsplit_kernel<<<dim3(NKVD/32, H_DIM/32), tb>>>(wv, wqkvt + (size_t)((NQD+NKVD)>>7)*112*16384,
                                                   H_DIM, NKVD, NKVD);
    tsplit_kernel<<<dim3(H_DIM/32, NQD/32),  tb>>>(wo, wot, NQD, H_DIM, H_DIM);
    tsplit_kernel<<<dim3(I_DIM/32, H_DIM/32), tb>>>(wg, wgut, H_DIM, I_DIM, I_DIM);
    tsplit_kernel<<<dim3(I_DIM/32, H_DIM/32), tb>>>(wu, wgut + (size_t)(I_DIM>>7)*112*16384,
                                                    H_DIM, I_DIM, I_DIM);
    tsplit_kernel<<<dim3(H_DIM/32, I_DIM/32), tb>>>(wd, wdt, I_DIM, H_DIM, H_DIM);

    // 1) pre-attn norm
    rmsnorm_split_kernel<<<S_LEN, 256>>>(x, w_in, ht);

    // 2) fused QKV projection
    gemm_mma<0,0><<<dim3(16, QKVD/256, 1), 256, GEMM_SMEM>>>(
        ht, wqkvt, qkv_, nullptr, 112, 112, 112, QKVD, 0, 0, 0, 0, 1, 0);

    // 3) RoPE; V transpose
    rope_split_kernel<<<S_LEN, 256>>>(qkv_, qt, kt);
    tsplit_kernel<<<dim3(NKVD/32, S_LEN/32), tb>>>(qkv_ + NQD + NKVD, vt,
                                                   S_LEN, NKVD, QKVD);

    // 4) scores = Q K^T per head (causal tile skip); kv head = z/2
    gemm_mma<1,0><<<dim3(16, S_LEN/256, NH), 256, GEMM_SMEM>>>(
        qt, kt, sc_, nullptr, 8, 128, 64, S_LEN, 0, SS, 8, 8, 2, 0);

    // 5) softcap + softmax -> tiled P
    softmax_split_kernel<<<dim3(S_LEN, NH), 256>>>(sc_, pt);

    // 6) attn = P @ V^T per head (K clipped; tiled output); kv head = z/2
    gemm_mma<2,1><<<dim3(16, 1, NH), 256, GEMM_SMEM>>>(
        pt, vt, nullptr, att, 64, 64, 64, 0, 128, 0, 1024, 128, 2, 256);

    // 7) output projection
    gemm_mma<0,0><<<dim3(16, H_DIM/256, 1), 256, GEMM_SMEM>>>(
        att, wot, tm_, nullptr, 128, 128, 128, H_DIM, 0, 0, 0, 0, 1, 0);

    // 8) x1 = x + rms_norm(attn_out)
    add_rmsnorm_kernel<<<S_LEN, 256>>>(x, tm_, w_pa, x1_);

    // 9) pre-FF norm
    rmsnorm_split_kernel<<<S_LEN, 256>>>(x1_, w_pf, ht);

    // 10) fused gate|up projection
    gemm_mma<0,0><<<dim3(16, GUD/256, 1), 256, GEMM_SMEM>>>(
        ht, wgut, gu_, nullptr, 112, 112, 112, GUD, 0, 0, 0, 0, 1, 0);

    // 11) gelu_tanh(gate) * up
    gelumul_split_kernel<<<dim3(I_DIM/(256*4), S_LEN), 256>>>(gu_, gut);

    // 12) down projection
    gemm_mma<0,0><<<dim3(16, H_DIM/256, 1), 256, GEMM_SMEM>>>(
        gut, wdt, tm_, nullptr, 448, 448, 448, H_DIM, 0, 0, 0, 0, 1, 0);

    // 13) out = x1 + rms_norm(ff_out)
    add_rmsnorm_kernel<<<S_LEN, 256>>>(x1_, tm_, w_pff, (float*)d_out);

    (void)n_in; (void)out_size;
}